// round 7
// baseline (speedup 1.0000x reference)
#include <cuda_runtime.h>
#include <cuda_fp16.h>
#include <cuda_bf16.h>
#include <cstdint>

// Problem constants
#define T_LEN 512
#define BATCH 32
#define DIM   512   // D == H
#define G4    2048  // 4*H
#define NCTA_DIR 64 // recurrence CTAs per direction (8 H-cols each)

// Scratch
__device__ float g_xpre[(size_t)2 * T_LEN * G4 * BATCH]; // [dir][t][g][b]
__device__ int   g_flags[2 * T_LEN * NCTA_DIR];          // per-(dir,step,cta) flags

// fp16 split scratch for phase-1 GEMM: x hi/lo, W single
__device__ __half g_xhi[(size_t)16384 * 512];
__device__ __half g_xlo[(size_t)16384 * 512];
__device__ __half g_wf [(size_t)4096 * 512];

// h history in split fp16: [dir][t][b][512]
__device__ __half g_hhi[(size_t)2 * T_LEN * BATCH * DIM];
__device__ __half g_hlo[(size_t)2 * T_LEN * BATCH * DIM];

__device__ __forceinline__ uint32_t smem_to_u32(const void* p) {
    uint32_t a;
    asm("{ .reg .u64 t; cvta.to.shared.u64 t, %1; cvt.u32.u64 %0, t; }" : "=r"(a) : "l"(p));
    return a;
}

#define CP_ASYNC16(dst, src) \
    asm volatile("cp.async.cg.shared.global [%0], [%1], 16;" :: "r"(dst), "l"(src) : "memory")
#define CP_COMMIT() asm volatile("cp.async.commit_group;" ::: "memory")
#define CP_WAIT2()  asm volatile("cp.async.wait_group 2;" ::: "memory")
#define CP_WAIT0()  asm volatile("cp.async.wait_group 0;" ::: "memory")

#define LDMATRIX_X4(r0, r1, r2, r3, addr) \
    asm volatile("ldmatrix.sync.aligned.m8n8.x4.shared.b16 {%0,%1,%2,%3}, [%4];" \
        : "=r"(r0), "=r"(r1), "=r"(r2), "=r"(r3) : "r"(addr))
#define LDMATRIX_X2(r0, r1, addr) \
    asm volatile("ldmatrix.sync.aligned.m8n8.x2.shared.b16 {%0,%1}, [%2];" \
        : "=r"(r0), "=r"(r1) : "r"(addr))

#define MMA_F16(d, a, b) \
    asm volatile("mma.sync.aligned.m16n8k16.row.col.f32.f16.f16.f32 " \
        "{%0,%1,%2,%3}, {%4,%5,%6,%7}, {%8,%9}, {%0,%1,%2,%3};" \
        : "+f"((d)[0]), "+f"((d)[1]), "+f"((d)[2]), "+f"((d)[3]) \
        : "r"((a)[0]), "r"((a)[1]), "r"((a)[2]), "r"((a)[3]), "r"((b)[0]), "r"((b)[1]))

// pack two fp32 into f16x2 (low half = a, high half = b)
__device__ __forceinline__ uint32_t pack_f16(float a, float b) {
    uint32_t r;
    asm("cvt.rn.f16x2.f32 %0, %1, %2;" : "=r"(r) : "f"(b), "f"(a));
    return r;
}

// ---------------------------------------------------------------------------
__global__ void init_flags_kernel() {
    int i = blockIdx.x * blockDim.x + threadIdx.x;
    if (i < 2 * T_LEN * NCTA_DIR) g_flags[i] = 0;
}

// fp32 -> fp16 hi/lo split
__global__ void splith_kernel(const float* __restrict__ src,
                              __half* __restrict__ hi,
                              __half* __restrict__ lo, int n) {
    int i = (blockIdx.x * blockDim.x + threadIdx.x) * 4;
    if (i >= n) return;
    float4 v = *(const float4*)(src + i);
    float vs[4] = {v.x, v.y, v.z, v.w};
#pragma unroll
    for (int j = 0; j < 4; j++) {
        __half h = __float2half_rn(vs[j]);
        hi[i + j] = h;
        lo[i + j] = __float2half_rn(vs[j] - __half2float(h));
    }
}

// fp32 -> fp16 single
__global__ void cvt_kernel(const float* __restrict__ src,
                           __half* __restrict__ dst, int n) {
    int i = (blockIdx.x * blockDim.x + threadIdx.x) * 4;
    if (i >= n) return;
    float4 v = *(const float4*)(src + i);
    dst[i + 0] = __float2half_rn(v.x);
    dst[i + 1] = __float2half_rn(v.y);
    dst[i + 2] = __float2half_rn(v.z);
    dst[i + 3] = __float2half_rn(v.w);
}

// ---------------------------------------------------------------------------
// Phase 1: HMMA fp16 2-pass GEMM for x_pre.
//   A = W (single fp16), B = x (hi/lo fp16). C = W·x_hi + W·x_lo.
//   CTA tile 128g x 128m, KC=32, 4 stages (3 in flight), 3 arrays/stage.
// ---------------------------------------------------------------------------
#define KC1 32
#define RPAD1 40                       // fp16 per padded row (80B)
#define ARR1 (128 * RPAD1 * 2)         // 10240
#define STAGE1 (3 * ARR1)              // 30720
#define NCHUNK1 16

__global__ __launch_bounds__(256, 1)
void xpre_mma_kernel(const float* __restrict__ bih, const float* __restrict__ bhh)
{
    extern __shared__ char smem[];
    const uint32_t sb = smem_to_u32(smem);

    const int tid  = threadIdx.x;
    const int wid  = tid >> 5;
    const int lane = tid & 31;
    const int g0   = blockIdx.x * 128;
    const int m0   = blockIdx.y * 128;
    const int wg   = wid >> 1;
    const int wm   = wid & 1;

    const int grp = lane >> 2;
    const int tig = lane & 3;

    const int lrow = tid >> 1;
    const __half* gsrc[3] = {
        g_wf  + (size_t)(g0 + lrow) * 512,
        g_xhi + (size_t)(m0 + lrow) * 512,
        g_xlo + (size_t)(m0 + lrow) * 512
    };

    auto issue_chunk = [&](int kc) {
        const uint32_t stb = sb + (kc & 3) * STAGE1;
#pragma unroll
        for (int arr = 0; arr < 3; arr++) {
#pragma unroll
            for (int i = 0; i < 2; i++) {
                int seg = (tid & 1) * 2 + i;
                CP_ASYNC16(stb + arr * ARR1 + lrow * (RPAD1 * 2) + seg * 16,
                           gsrc[arr] + kc * KC1 + seg * 8);
            }
        }
        CP_COMMIT();
    };

    float acc[2][8][4];
#pragma unroll
    for (int mt = 0; mt < 2; mt++)
#pragma unroll
        for (int nt = 0; nt < 8; nt++)
#pragma unroll
            for (int r = 0; r < 4; r++) acc[mt][nt][r] = 0.f;

    issue_chunk(0);
    issue_chunk(1);
    issue_chunk(2);

    const uint32_t lm_row = (uint32_t)(lane & 15);
    const uint32_t lm_colb = (uint32_t)(lane >> 4) * 16;

    for (int kc = 0; kc < NCHUNK1; kc++) {
        const uint32_t stb = sb + (kc & 3) * STAGE1;
        CP_WAIT2();
        __syncthreads();

        const uint32_t AF  = stb;
        const uint32_t BHI = stb + ARR1;
        const uint32_t BLO = stb + 2 * ARR1;

#pragma unroll
        for (int kk = 0; kk < 2; kk++) {
            const uint32_t kb = lm_colb + kk * 32;

            uint32_t af[2][4], bb[4][4];
#pragma unroll
            for (int mt = 0; mt < 2; mt++) {
                uint32_t aoff = (wg * 32 + mt * 16 + lm_row) * (RPAD1 * 2) + kb;
                LDMATRIX_X4(af[mt][0], af[mt][1], af[mt][2], af[mt][3], AF + aoff);
            }
            // pass 1: W · x_hi
#pragma unroll
            for (int nt2 = 0; nt2 < 4; nt2++) {
                uint32_t boff = (wm * 64 + nt2 * 16 + lm_row) * (RPAD1 * 2) + kb;
                LDMATRIX_X4(bb[nt2][0], bb[nt2][1], bb[nt2][2], bb[nt2][3], BHI + boff);
            }
#pragma unroll
            for (int mt = 0; mt < 2; mt++)
#pragma unroll
                for (int nt = 0; nt < 8; nt++) {
                    uint32_t bfrag[2] = { bb[nt >> 1][nt & 1], bb[nt >> 1][(nt & 1) + 2] };
                    MMA_F16(acc[mt][nt], af[mt], bfrag);
                }
            // pass 2: W · x_lo
#pragma unroll
            for (int nt2 = 0; nt2 < 4; nt2++) {
                uint32_t boff = (wm * 64 + nt2 * 16 + lm_row) * (RPAD1 * 2) + kb;
                LDMATRIX_X4(bb[nt2][0], bb[nt2][1], bb[nt2][2], bb[nt2][3], BLO + boff);
            }
#pragma unroll
            for (int mt = 0; mt < 2; mt++)
#pragma unroll
                for (int nt = 0; nt < 8; nt++) {
                    uint32_t bfrag[2] = { bb[nt >> 1][nt & 1], bb[nt >> 1][(nt & 1) + 2] };
                    MMA_F16(acc[mt][nt], af[mt], bfrag);
                }
        }
        __syncthreads();
        if (kc + 3 < NCHUNK1) issue_chunk(kc + 3);
    }

    float bias[2][2];
    float* rowp[2][2];
#pragma unroll
    for (int mt = 0; mt < 2; mt++)
#pragma unroll
        for (int hf = 0; hf < 2; hf++) {
            int g = g0 + wg * 32 + mt * 16 + hf * 8 + grp;
            bias[mt][hf] = bih[g] + bhh[g];
            int d = g >> 11, gp = g & 2047;
            rowp[mt][hf] = g_xpre + ((size_t)d * T_LEN) * (G4 * BATCH) + (size_t)gp * BATCH;
        }
#pragma unroll
    for (int mt = 0; mt < 2; mt++)
#pragma unroll
        for (int nt = 0; nt < 8; nt++) {
            int m = m0 + wm * 64 + nt * 8 + 2 * tig;
            int t = m >> 5, b = m & 31;
            size_t toff = (size_t)t * (G4 * BATCH) + b;
            float2 v0 = { acc[mt][nt][0] + bias[mt][0], acc[mt][nt][1] + bias[mt][0] };
            float2 v1 = { acc[mt][nt][2] + bias[mt][1], acc[mt][nt][3] + bias[mt][1] };
            *(float2*)(rowp[mt][0] + toff) = v0;
            *(float2*)(rowp[mt][1] + toff) = v1;
        }
}

// ---------------------------------------------------------------------------
// Phase 2 v4: persistent recurrence, fp16 2-pass, per-CTA flag signaling.
//   Warp = (mhalf, kgroup): 16 batches x 32 gate rows x 128 k-slice.
//   W single fp16 fragments preloaded; h split fp16 hi/lo via warp-local
//   cp.async; h stores staged through smem for coalescing.
// ---------------------------------------------------------------------------
#define KPAD 520
#define WF_OFF  0
#define HHI_OFF (32 * KPAD * 2)            // 33280
#define HLO_OFF (2 * 32 * KPAD * 2)        // 66560
#define KGB_OFF (3 * 32 * KPAD * 2)        // 99840
#define XPS_OFF (KGB_OFF + 4 * 32 * 33 * 4)// 116736
#define CSL_OFF (XPS_OFF + 32 * 36 * 4)    // 121344
#define HST_OFF (CSL_OFF + 8 * 32 * 4)     // 122368 (hi 512B, lo 512B)
#define SMEM2_TOTAL (HST_OFF + 1024)

__global__ __launch_bounds__(256, 1)
void lstm_rec_mma_kernel(const float* __restrict__ h0,
                         const float* __restrict__ c0,
                         const float* __restrict__ Whh,
                         float* __restrict__ out,
                         float* __restrict__ hout,
                         float* __restrict__ cout)
{
    extern __shared__ char smraw[];
    const uint32_t sb = smem_to_u32(smraw);
    float* kgb = (float*)(smraw + KGB_OFF);
    float* xps = (float*)(smraw + XPS_OFF);
    float* csl = (float*)(smraw + CSL_OFF);
    __half* hst_hi = (__half*)(smraw + HST_OFF);        // [32][8]
    __half* hst_lo = (__half*)(smraw + HST_OFF + 512);  // [32][8]
    uint32_t* Wf32  = (uint32_t*)(smraw + WF_OFF);
    uint32_t* Hhi32 = (uint32_t*)(smraw + HHI_OFF);
    uint32_t* Hlo32 = (uint32_t*)(smraw + HLO_OFF);

    const int cta  = blockIdx.x;
    const int dir  = cta >> 6;
    const int slot = cta & (NCTA_DIR - 1);
    const int j0   = slot * 8;
    const int tid  = threadIdx.x;
    const int wid  = tid >> 5;
    const int lane = tid & 31;
    const int mhalf = wid >> 2;
    const int kg    = wid & 3;
    const int m0w   = mhalf * 16;

    // ---- convert W_hh slice into smem fp16 ----
    {
        int lr = tid >> 3, seg = tid & 7;
        int gr = (lr >> 3) * DIM + j0 + (lr & 7);
        const float4* src = (const float4*)(Whh + ((size_t)dir * G4 + gr) * DIM + seg * 64);
#pragma unroll
        for (int i = 0; i < 16; i++) {
            float4 v = src[i];
            int k = seg * 64 + i * 4;
            int u = (lr * KPAD + k) >> 1;
            Wf32[u]     = pack_f16(v.x, v.y);
            Wf32[u + 1] = pack_f16(v.z, v.w);
        }
    }
    {
        int cc = tid >> 5, b = tid & 31;
        csl[cc * 32 + b] = c0[((size_t)dir * BATCH + b) * DIM + j0 + cc];
    }
    __syncthreads();

    // ---- preload W fragments (step-invariant): bw[nt][ks][2] ----
    uint32_t bw[4][8][2];
    {
        const uint32_t brow = (uint32_t)(lane & 7);
        const uint32_t bcol = (uint32_t)((lane >> 3) & 1) * 16;
#pragma unroll
        for (int nt = 0; nt < 4; nt++)
#pragma unroll
            for (int ks = 0; ks < 8; ks++) {
                uint32_t off = (nt * 8 + brow) * (KPAD * 2) + kg * 256 + ks * 32 + bcol;
                LDMATRIX_X2(bw[nt][ks][0], bw[nt][ks][1], sb + WF_OFF + off);
            }
    }

    const uint32_t arow_off = (uint32_t)(m0w + (lane & 15)) * (KPAD * 2)
                            + (uint32_t)kg * 256 + (uint32_t)(lane >> 4) * 16;

    const int cc_u = tid >> 5;
    const int b_u  = tid & 31;
    const int grp  = lane >> 2;
    const int tig  = lane & 3;

    for (int s = 0; s < T_LEN; s++) {
        const int t = dir ? (T_LEN - 1 - s) : s;

        // prefetch x_pre slice (independent of h) BEFORE the flag wait
        {
            int lr = tid >> 3, seg = tid & 7;
            int gp = (lr >> 3) * DIM + j0 + (lr & 7);
            const float* src = g_xpre + (size_t)dir * ((size_t)T_LEN * G4 * BATCH)
                             + (size_t)t * (G4 * BATCH) + (size_t)gp * BATCH + seg * 4;
            CP_ASYNC16(sb + XPS_OFF + (uint32_t)(lr * 144 + seg * 16), src);
            CP_COMMIT();
        }

        if (s == 0) {
            const float4* h0p = (const float4*)(h0 + (size_t)dir * BATCH * DIM);
#pragma unroll
            for (int it = 0; it < 16; it++) {
                int idx = tid + it * 256;
                int b = idx >> 7, c4 = (idx & 127) * 4;
                float4 v = h0p[idx];
                float f0 = __half2float(__float2half_rn(v.x));
                float f1 = __half2float(__float2half_rn(v.y));
                float f2 = __half2float(__float2half_rn(v.z));
                float f3 = __half2float(__float2half_rn(v.w));
                int u = (b * KPAD + c4) >> 1;
                Hhi32[u]     = pack_f16(f0, f1);
                Hhi32[u + 1] = pack_f16(f2, f3);
                Hlo32[u]     = pack_f16(v.x - f0, v.y - f1);
                Hlo32[u + 1] = pack_f16(v.z - f2, v.w - f3);
            }
            CP_WAIT0();
            __syncthreads();
        } else {
            // per-CTA flag wait: 64 threads poll 64 producer flags in parallel
            if (tid < NCTA_DIR) {
                volatile int* f = &g_flags[(dir * T_LEN + (s - 1)) * NCTA_DIR + tid];
                while (*f == 0) { }
                __threadfence();
            }
            __syncthreads();
            // warp-local h cp.async: 16 batches x 128 k, hi+lo
            const int tp = dir ? (t + 1) : (t - 1);
            const __half* hh = g_hhi + (size_t)(dir * T_LEN + tp) * (BATCH * DIM);
            const __half* hl = g_hlo + (size_t)(dir * T_LEN + tp) * (BATCH * DIM);
#pragma unroll
            for (int it = 0; it < 8; it++) {
                int u = lane + it * 32;
                int r = u >> 4, sg = u & 15;
                int row = m0w + r;
                size_t goff = (size_t)row * DIM + kg * 128 + sg * 8;
                uint32_t doff = (uint32_t)(row * KPAD + kg * 128 + sg * 8) * 2;
                CP_ASYNC16(sb + HHI_OFF + doff, hh + goff);
                CP_ASYNC16(sb + HLO_OFF + doff, hl + goff);
            }
            CP_COMMIT();
            CP_WAIT0();   // per-warp: no CTA barrier before MMA
        }

        // ---- MMA: (h_hi + h_lo) @ W^T, 2 passes ----
        float acc[4][4];
#pragma unroll
        for (int nt = 0; nt < 4; nt++)
#pragma unroll
            for (int r = 0; r < 4; r++) acc[nt][r] = 0.f;

#pragma unroll
        for (int ks = 0; ks < 8; ks++) {
            uint32_t a_h[4], a_l[4];
            LDMATRIX_X4(a_h[0], a_h[1], a_h[2], a_h[3], sb + HHI_OFF + arow_off + ks * 32);
            LDMATRIX_X4(a_l[0], a_l[1], a_l[2], a_l[3], sb + HLO_OFF + arow_off + ks * 32);
#pragma unroll
            for (int nt = 0; nt < 4; nt++) {
                MMA_F16(acc[nt], a_h, bw[nt][ks]);
                MMA_F16(acc[nt], a_l, bw[nt][ks]);
            }
        }

        // scatter partials to kgb[kg][n][b]
        {
            float* kb = kgb + kg * (32 * 33);
            int b1 = m0w + grp, b2 = b1 + 8;
#pragma unroll
            for (int nt = 0; nt < 4; nt++) {
                int na = nt * 8 + 2 * tig;
                kb[na * 33 + b1]       = acc[nt][0];
                kb[(na + 1) * 33 + b1] = acc[nt][1];
                kb[na * 33 + b2]       = acc[nt][2];
                kb[(na + 1) * 33 + b2] = acc[nt][3];
            }
        }
        __syncthreads();

        // ---- LSTM update: thread -> (cc_u, b_u); reduce 4 k-partials ----
        {
            float xi = xps[cc_u * 36 + b_u];
            float xf = xps[(8 + cc_u) * 36 + b_u];
            float xg = xps[(16 + cc_u) * 36 + b_u];
            float xo = xps[(24 + cc_u) * 36 + b_u];
#pragma unroll
            for (int k = 0; k < 4; k++) {
                const float* kb = kgb + k * (32 * 33);
                xi += kb[cc_u * 33 + b_u];
                xf += kb[(8 + cc_u) * 33 + b_u];
                xg += kb[(16 + cc_u) * 33 + b_u];
                xo += kb[(24 + cc_u) * 33 + b_u];
            }
            float ig = 1.f / (1.f + __expf(-xi));
            float fg = 1.f / (1.f + __expf(-xf));
            float gg = tanhf(xg);
            float og = 1.f / (1.f + __expf(-xo));
            float c  = fg * csl[cc_u * 32 + b_u] + ig * gg;
            csl[cc_u * 32 + b_u] = c;
            float h  = og * tanhf(c);

            out[(size_t)t * (BATCH * 1024) + (size_t)b_u * 1024 + dir * DIM + j0 + cc_u] = h;

            // stage split h into smem for coalesced store
            __half hh = __float2half_rn(h);
            hst_hi[b_u * 8 + cc_u] = hh;
            hst_lo[b_u * 8 + cc_u] = __float2half_rn(h - __half2float(hh));

            if (s == T_LEN - 1) {
                hout[((size_t)dir * BATCH + b_u) * DIM + j0 + cc_u] = h;
                cout[((size_t)dir * BATCH + b_u) * DIM + j0 + cc_u] = c;
            }
        }
        __syncthreads();

        // coalesced h history store: warp 0 = hi, warp 1 = lo (16B per lane)
        {
            const size_t hbase = (size_t)(dir * T_LEN + t) * (BATCH * DIM) + j0;
            if (wid == 0) {
                uint4 v = *(uint4*)&hst_hi[lane * 8];
                *(uint4*)(g_hhi + hbase + (size_t)lane * DIM) = v;
            } else if (wid == 1) {
                uint4 v = *(uint4*)&hst_lo[lane * 8];
                *(uint4*)(g_hlo + hbase + (size_t)lane * DIM) = v;
            }
        }
        __syncthreads();

        if (tid == 0) {
            __threadfence();
            *(volatile int*)&g_flags[(dir * T_LEN + s) * NCTA_DIR + slot] = 1;
        }
    }
}

// ---------------------------------------------------------------------------
// launch
// ---------------------------------------------------------------------------
extern "C" void kernel_launch(void* const* d_in, const int* in_sizes, int n_in,
                              void* d_out, int out_size)
{
    (void)in_sizes; (void)n_in; (void)out_size;
    const float* x   = (const float*)d_in[0];
    const float* h0  = (const float*)d_in[1];
    const float* c0  = (const float*)d_in[2];
    const float* Wih = (const float*)d_in[3];
    const float* bih = (const float*)d_in[4];
    const float* Whh = (const float*)d_in[5];
    const float* bhh = (const float*)d_in[6];

    float* out  = (float*)d_out;
    float* hout = out + (size_t)T_LEN * BATCH * 1024;
    float* cout = hout + (size_t)2 * BATCH * DIM;

    init_flags_kernel<<<(2 * T_LEN * NCTA_DIR + 255) / 256, 256>>>();

    __half *xhi, *xlo, *wf;
    cudaGetSymbolAddress((void**)&xhi, g_xhi);
    cudaGetSymbolAddress((void**)&xlo, g_xlo);
    cudaGetSymbolAddress((void**)&wf,  g_wf);
    {
        int nx = 16384 * 512;
        splith_kernel<<<nx / 4 / 256, 256>>>(x, xhi, xlo, nx);
        int nw = 4096 * 512;
        cvt_kernel<<<nw / 4 / 256, 256>>>(Wih, wf, nw);
    }

    {
        size_t smem = 4 * STAGE1;
        cudaFuncSetAttribute(xpre_mma_kernel,
                             cudaFuncAttributeMaxDynamicSharedMemorySize, (int)smem);
        dim3 grid(4096 / 128, 16384 / 128);
        xpre_mma_kernel<<<grid, 256, smem>>>(bih, bhh);
    }

    {
        cudaFuncSetAttribute(lstm_rec_mma_kernel,
                             cudaFuncAttributeMaxDynamicSharedMemorySize, SMEM2_TOTAL);
        lstm_rec_mma_kernel<<<2 * NCTA_DIR, 256, SMEM2_TOTAL>>>(h0, c0, Whh, out, hout, cout);
    }
}

// round 8
// speedup vs baseline: 1.0018x; 1.0018x over previous
#include <cuda_runtime.h>
#include <cuda_fp16.h>
#include <cuda_bf16.h>
#include <cstdint>

// Problem constants
#define T_LEN 512
#define BATCH 32
#define DIM   512   // D == H
#define G4    2048  // 4*H
#define NCTA_DIR 64 // recurrence CTAs per direction (8 H-cols each)

// Scratch
__device__ float g_xpre[(size_t)2 * T_LEN * G4 * BATCH]; // [dir][t][g][b]
__device__ int   g_flags[2 * T_LEN * NCTA_DIR];          // per-(dir,step,cta) flags

// fp16 split scratch for phase-1 GEMM: x hi/lo, W single
__device__ __half g_xhi[(size_t)16384 * 512];
__device__ __half g_xlo[(size_t)16384 * 512];
__device__ __half g_wf [(size_t)4096 * 512];

// h history in split fp16: [dir][t][b][512]
__device__ __half g_hhi[(size_t)2 * T_LEN * BATCH * DIM];
__device__ __half g_hlo[(size_t)2 * T_LEN * BATCH * DIM];

__device__ __forceinline__ uint32_t smem_to_u32(const void* p) {
    uint32_t a;
    asm("{ .reg .u64 t; cvta.to.shared.u64 t, %1; cvt.u32.u64 %0, t; }" : "=r"(a) : "l"(p));
    return a;
}

#define CP_ASYNC16(dst, src) \
    asm volatile("cp.async.cg.shared.global [%0], [%1], 16;" :: "r"(dst), "l"(src) : "memory")
#define CP_COMMIT() asm volatile("cp.async.commit_group;" ::: "memory")
#define CP_WAIT2()  asm volatile("cp.async.wait_group 2;" ::: "memory")
#define CP_WAIT0()  asm volatile("cp.async.wait_group 0;" ::: "memory")

#define LDMATRIX_X4(r0, r1, r2, r3, addr) \
    asm volatile("ldmatrix.sync.aligned.m8n8.x4.shared.b16 {%0,%1,%2,%3}, [%4];" \
        : "=r"(r0), "=r"(r1), "=r"(r2), "=r"(r3) : "r"(addr))
#define LDMATRIX_X2(r0, r1, addr) \
    asm volatile("ldmatrix.sync.aligned.m8n8.x2.shared.b16 {%0,%1}, [%2];" \
        : "=r"(r0), "=r"(r1) : "r"(addr))

#define MMA_F16(d, a, b) \
    asm volatile("mma.sync.aligned.m16n8k16.row.col.f32.f16.f16.f32 " \
        "{%0,%1,%2,%3}, {%4,%5,%6,%7}, {%8,%9}, {%0,%1,%2,%3};" \
        : "+f"((d)[0]), "+f"((d)[1]), "+f"((d)[2]), "+f"((d)[3]) \
        : "r"((a)[0]), "r"((a)[1]), "r"((a)[2]), "r"((a)[3]), "r"((b)[0]), "r"((b)[1]))

// pack two fp32 into f16x2 (low half = a, high half = b)
__device__ __forceinline__ uint32_t pack_f16(float a, float b) {
    uint32_t r;
    asm("cvt.rn.f16x2.f32 %0, %1, %2;" : "=r"(r) : "f"(b), "f"(a));
    return r;
}

// ---------------------------------------------------------------------------
__global__ void init_flags_kernel() {
    int i = blockIdx.x * blockDim.x + threadIdx.x;
    if (i < 2 * T_LEN * NCTA_DIR) g_flags[i] = 0;
}

// fp32 -> fp16 hi/lo split
__global__ void splith_kernel(const float* __restrict__ src,
                              __half* __restrict__ hi,
                              __half* __restrict__ lo, int n) {
    int i = (blockIdx.x * blockDim.x + threadIdx.x) * 4;
    if (i >= n) return;
    float4 v = *(const float4*)(src + i);
    float vs[4] = {v.x, v.y, v.z, v.w};
#pragma unroll
    for (int j = 0; j < 4; j++) {
        __half h = __float2half_rn(vs[j]);
        hi[i + j] = h;
        lo[i + j] = __float2half_rn(vs[j] - __half2float(h));
    }
}

// fp32 -> fp16 single
__global__ void cvt_kernel(const float* __restrict__ src,
                           __half* __restrict__ dst, int n) {
    int i = (blockIdx.x * blockDim.x + threadIdx.x) * 4;
    if (i >= n) return;
    float4 v = *(const float4*)(src + i);
    dst[i + 0] = __float2half_rn(v.x);
    dst[i + 1] = __float2half_rn(v.y);
    dst[i + 2] = __float2half_rn(v.z);
    dst[i + 3] = __float2half_rn(v.w);
}

// ---------------------------------------------------------------------------
// Phase 1: HMMA fp16 2-pass GEMM for x_pre.
//   A = W (single fp16), B = x (hi/lo fp16). C = W·x_hi + W·x_lo.
//   CTA tile 128g x 128m, KC=32, 4 stages (3 in flight), 3 arrays/stage.
// ---------------------------------------------------------------------------
#define KC1 32
#define RPAD1 40                       // fp16 per padded row (80B)
#define ARR1 (128 * RPAD1 * 2)         // 10240
#define STAGE1 (3 * ARR1)              // 30720
#define NCHUNK1 16

__global__ __launch_bounds__(256, 1)
void xpre_mma_kernel(const float* __restrict__ bih, const float* __restrict__ bhh)
{
    extern __shared__ char smem[];
    const uint32_t sb = smem_to_u32(smem);

    const int tid  = threadIdx.x;
    const int wid  = tid >> 5;
    const int lane = tid & 31;
    const int g0   = blockIdx.x * 128;
    const int m0   = blockIdx.y * 128;
    const int wg   = wid >> 1;
    const int wm   = wid & 1;

    const int grp = lane >> 2;
    const int tig = lane & 3;

    const int lrow = tid >> 1;
    const __half* gsrc[3] = {
        g_wf  + (size_t)(g0 + lrow) * 512,
        g_xhi + (size_t)(m0 + lrow) * 512,
        g_xlo + (size_t)(m0 + lrow) * 512
    };

    auto issue_chunk = [&](int kc) {
        const uint32_t stb = sb + (kc & 3) * STAGE1;
#pragma unroll
        for (int arr = 0; arr < 3; arr++) {
#pragma unroll
            for (int i = 0; i < 2; i++) {
                int seg = (tid & 1) * 2 + i;
                CP_ASYNC16(stb + arr * ARR1 + lrow * (RPAD1 * 2) + seg * 16,
                           gsrc[arr] + kc * KC1 + seg * 8);
            }
        }
        CP_COMMIT();
    };

    float acc[2][8][4];
#pragma unroll
    for (int mt = 0; mt < 2; mt++)
#pragma unroll
        for (int nt = 0; nt < 8; nt++)
#pragma unroll
            for (int r = 0; r < 4; r++) acc[mt][nt][r] = 0.f;

    issue_chunk(0);
    issue_chunk(1);
    issue_chunk(2);

    const uint32_t lm_row = (uint32_t)(lane & 15);
    const uint32_t lm_colb = (uint32_t)(lane >> 4) * 16;

    for (int kc = 0; kc < NCHUNK1; kc++) {
        const uint32_t stb = sb + (kc & 3) * STAGE1;
        CP_WAIT2();
        __syncthreads();

        const uint32_t AF  = stb;
        const uint32_t BHI = stb + ARR1;
        const uint32_t BLO = stb + 2 * ARR1;

#pragma unroll
        for (int kk = 0; kk < 2; kk++) {
            const uint32_t kb = lm_colb + kk * 32;

            uint32_t af[2][4], bb[4][4];
#pragma unroll
            for (int mt = 0; mt < 2; mt++) {
                uint32_t aoff = (wg * 32 + mt * 16 + lm_row) * (RPAD1 * 2) + kb;
                LDMATRIX_X4(af[mt][0], af[mt][1], af[mt][2], af[mt][3], AF + aoff);
            }
            // pass 1: W · x_hi
#pragma unroll
            for (int nt2 = 0; nt2 < 4; nt2++) {
                uint32_t boff = (wm * 64 + nt2 * 16 + lm_row) * (RPAD1 * 2) + kb;
                LDMATRIX_X4(bb[nt2][0], bb[nt2][1], bb[nt2][2], bb[nt2][3], BHI + boff);
            }
#pragma unroll
            for (int mt = 0; mt < 2; mt++)
#pragma unroll
                for (int nt = 0; nt < 8; nt++) {
                    uint32_t bfrag[2] = { bb[nt >> 1][nt & 1], bb[nt >> 1][(nt & 1) + 2] };
                    MMA_F16(acc[mt][nt], af[mt], bfrag);
                }
            // pass 2: W · x_lo
#pragma unroll
            for (int nt2 = 0; nt2 < 4; nt2++) {
                uint32_t boff = (wm * 64 + nt2 * 16 + lm_row) * (RPAD1 * 2) + kb;
                LDMATRIX_X4(bb[nt2][0], bb[nt2][1], bb[nt2][2], bb[nt2][3], BLO + boff);
            }
#pragma unroll
            for (int mt = 0; mt < 2; mt++)
#pragma unroll
                for (int nt = 0; nt < 8; nt++) {
                    uint32_t bfrag[2] = { bb[nt >> 1][nt & 1], bb[nt >> 1][(nt & 1) + 2] };
                    MMA_F16(acc[mt][nt], af[mt], bfrag);
                }
        }
        __syncthreads();
        if (kc + 3 < NCHUNK1) issue_chunk(kc + 3);
    }

    float bias[2][2];
    float* rowp[2][2];
#pragma unroll
    for (int mt = 0; mt < 2; mt++)
#pragma unroll
        for (int hf = 0; hf < 2; hf++) {
            int g = g0 + wg * 32 + mt * 16 + hf * 8 + grp;
            bias[mt][hf] = bih[g] + bhh[g];
            int d = g >> 11, gp = g & 2047;
            rowp[mt][hf] = g_xpre + ((size_t)d * T_LEN) * (G4 * BATCH) + (size_t)gp * BATCH;
        }
#pragma unroll
    for (int mt = 0; mt < 2; mt++)
#pragma unroll
        for (int nt = 0; nt < 8; nt++) {
            int m = m0 + wm * 64 + nt * 8 + 2 * tig;
            int t = m >> 5, b = m & 31;
            size_t toff = (size_t)t * (G4 * BATCH) + b;
            float2 v0 = { acc[mt][nt][0] + bias[mt][0], acc[mt][nt][1] + bias[mt][0] };
            float2 v1 = { acc[mt][nt][2] + bias[mt][1], acc[mt][nt][3] + bias[mt][1] };
            *(float2*)(rowp[mt][0] + toff) = v0;
            *(float2*)(rowp[mt][1] + toff) = v1;
        }
}

// ---------------------------------------------------------------------------
// Phase 2 v4: persistent recurrence, fp16 2-pass, per-CTA flag signaling.
//   Warp = (mhalf, kgroup): 16 batches x 32 gate rows x 128 k-slice.
//   W single fp16 fragments preloaded; h split fp16 hi/lo via warp-local
//   cp.async; h stores staged through smem for coalescing.
// ---------------------------------------------------------------------------
#define KPAD 520
#define WF_OFF  0
#define HHI_OFF (32 * KPAD * 2)            // 33280
#define HLO_OFF (2 * 32 * KPAD * 2)        // 66560
#define KGB_OFF (3 * 32 * KPAD * 2)        // 99840
#define XPS_OFF (KGB_OFF + 4 * 32 * 33 * 4)// 116736
#define CSL_OFF (XPS_OFF + 32 * 36 * 4)    // 121344
#define HST_OFF (CSL_OFF + 8 * 32 * 4)     // 122368 (hi 512B, lo 512B)
#define SMEM2_TOTAL (HST_OFF + 1024)

__global__ __launch_bounds__(256, 1)
void lstm_rec_mma_kernel(const float* __restrict__ h0,
                         const float* __restrict__ c0,
                         const float* __restrict__ Whh,
                         float* __restrict__ out,
                         float* __restrict__ hout,
                         float* __restrict__ cout)
{
    extern __shared__ char smraw[];
    const uint32_t sb = smem_to_u32(smraw);
    float* kgb = (float*)(smraw + KGB_OFF);
    float* xps = (float*)(smraw + XPS_OFF);
    float* csl = (float*)(smraw + CSL_OFF);
    __half* hst_hi = (__half*)(smraw + HST_OFF);        // [32][8]
    __half* hst_lo = (__half*)(smraw + HST_OFF + 512);  // [32][8]
    uint32_t* Wf32  = (uint32_t*)(smraw + WF_OFF);
    uint32_t* Hhi32 = (uint32_t*)(smraw + HHI_OFF);
    uint32_t* Hlo32 = (uint32_t*)(smraw + HLO_OFF);

    const int cta  = blockIdx.x;
    const int dir  = cta >> 6;
    const int slot = cta & (NCTA_DIR - 1);
    const int j0   = slot * 8;
    const int tid  = threadIdx.x;
    const int wid  = tid >> 5;
    const int lane = tid & 31;
    const int mhalf = wid >> 2;
    const int kg    = wid & 3;
    const int m0w   = mhalf * 16;

    // ---- convert W_hh slice into smem fp16 ----
    {
        int lr = tid >> 3, seg = tid & 7;
        int gr = (lr >> 3) * DIM + j0 + (lr & 7);
        const float4* src = (const float4*)(Whh + ((size_t)dir * G4 + gr) * DIM + seg * 64);
#pragma unroll
        for (int i = 0; i < 16; i++) {
            float4 v = src[i];
            int k = seg * 64 + i * 4;
            int u = (lr * KPAD + k) >> 1;
            Wf32[u]     = pack_f16(v.x, v.y);
            Wf32[u + 1] = pack_f16(v.z, v.w);
        }
    }
    {
        int cc = tid >> 5, b = tid & 31;
        csl[cc * 32 + b] = c0[((size_t)dir * BATCH + b) * DIM + j0 + cc];
    }
    __syncthreads();

    // ---- preload W fragments (step-invariant): bw[nt][ks][2] ----
    uint32_t bw[4][8][2];
    {
        const uint32_t brow = (uint32_t)(lane & 7);
        const uint32_t bcol = (uint32_t)((lane >> 3) & 1) * 16;
#pragma unroll
        for (int nt = 0; nt < 4; nt++)
#pragma unroll
            for (int ks = 0; ks < 8; ks++) {
                uint32_t off = (nt * 8 + brow) * (KPAD * 2) + kg * 256 + ks * 32 + bcol;
                LDMATRIX_X2(bw[nt][ks][0], bw[nt][ks][1], sb + WF_OFF + off);
            }
    }

    const uint32_t arow_off = (uint32_t)(m0w + (lane & 15)) * (KPAD * 2)
                            + (uint32_t)kg * 256 + (uint32_t)(lane >> 4) * 16;

    const int cc_u = tid >> 5;
    const int b_u  = tid & 31;
    const int grp  = lane >> 2;
    const int tig  = lane & 3;

    for (int s = 0; s < T_LEN; s++) {
        const int t = dir ? (T_LEN - 1 - s) : s;

        // prefetch x_pre slice (independent of h) BEFORE the flag wait
        {
            int lr = tid >> 3, seg = tid & 7;
            int gp = (lr >> 3) * DIM + j0 + (lr & 7);
            const float* src = g_xpre + (size_t)dir * ((size_t)T_LEN * G4 * BATCH)
                             + (size_t)t * (G4 * BATCH) + (size_t)gp * BATCH + seg * 4;
            CP_ASYNC16(sb + XPS_OFF + (uint32_t)(lr * 144 + seg * 16), src);
            CP_COMMIT();
        }

        if (s == 0) {
            const float4* h0p = (const float4*)(h0 + (size_t)dir * BATCH * DIM);
#pragma unroll
            for (int it = 0; it < 16; it++) {
                int idx = tid + it * 256;
                int b = idx >> 7, c4 = (idx & 127) * 4;
                float4 v = h0p[idx];
                float f0 = __half2float(__float2half_rn(v.x));
                float f1 = __half2float(__float2half_rn(v.y));
                float f2 = __half2float(__float2half_rn(v.z));
                float f3 = __half2float(__float2half_rn(v.w));
                int u = (b * KPAD + c4) >> 1;
                Hhi32[u]     = pack_f16(f0, f1);
                Hhi32[u + 1] = pack_f16(f2, f3);
                Hlo32[u]     = pack_f16(v.x - f0, v.y - f1);
                Hlo32[u + 1] = pack_f16(v.z - f2, v.w - f3);
            }
            CP_WAIT0();
            __syncthreads();
        } else {
            // per-CTA flag wait: 64 threads poll 64 producer flags in parallel
            if (tid < NCTA_DIR) {
                volatile int* f = &g_flags[(dir * T_LEN + (s - 1)) * NCTA_DIR + tid];
                while (*f == 0) { }
                __threadfence();
            }
            __syncthreads();
            // warp-local h cp.async: 16 batches x 128 k, hi+lo
            const int tp = dir ? (t + 1) : (t - 1);
            const __half* hh = g_hhi + (size_t)(dir * T_LEN + tp) * (BATCH * DIM);
            const __half* hl = g_hlo + (size_t)(dir * T_LEN + tp) * (BATCH * DIM);
#pragma unroll
            for (int it = 0; it < 8; it++) {
                int u = lane + it * 32;
                int r = u >> 4, sg = u & 15;
                int row = m0w + r;
                size_t goff = (size_t)row * DIM + kg * 128 + sg * 8;
                uint32_t doff = (uint32_t)(row * KPAD + kg * 128 + sg * 8) * 2;
                CP_ASYNC16(sb + HHI_OFF + doff, hh + goff);
                CP_ASYNC16(sb + HLO_OFF + doff, hl + goff);
            }
            CP_COMMIT();
            CP_WAIT0();   // per-warp: no CTA barrier before MMA
        }

        // ---- MMA: (h_hi + h_lo) @ W^T, 2 passes ----
        float acc[4][4];
#pragma unroll
        for (int nt = 0; nt < 4; nt++)
#pragma unroll
            for (int r = 0; r < 4; r++) acc[nt][r] = 0.f;

#pragma unroll
        for (int ks = 0; ks < 8; ks++) {
            uint32_t a_h[4], a_l[4];
            LDMATRIX_X4(a_h[0], a_h[1], a_h[2], a_h[3], sb + HHI_OFF + arow_off + ks * 32);
            LDMATRIX_X4(a_l[0], a_l[1], a_l[2], a_l[3], sb + HLO_OFF + arow_off + ks * 32);
#pragma unroll
            for (int nt = 0; nt < 4; nt++) {
                MMA_F16(acc[nt], a_h, bw[nt][ks]);
                MMA_F16(acc[nt], a_l, bw[nt][ks]);
            }
        }

        // scatter partials to kgb[kg][n][b]
        {
            float* kb = kgb + kg * (32 * 33);
            int b1 = m0w + grp, b2 = b1 + 8;
#pragma unroll
            for (int nt = 0; nt < 4; nt++) {
                int na = nt * 8 + 2 * tig;
                kb[na * 33 + b1]       = acc[nt][0];
                kb[(na + 1) * 33 + b1] = acc[nt][1];
                kb[na * 33 + b2]       = acc[nt][2];
                kb[(na + 1) * 33 + b2] = acc[nt][3];
            }
        }
        __syncthreads();

        // ---- LSTM update: thread -> (cc_u, b_u); reduce 4 k-partials ----
        {
            float xi = xps[cc_u * 36 + b_u];
            float xf = xps[(8 + cc_u) * 36 + b_u];
            float xg = xps[(16 + cc_u) * 36 + b_u];
            float xo = xps[(24 + cc_u) * 36 + b_u];
#pragma unroll
            for (int k = 0; k < 4; k++) {
                const float* kb = kgb + k * (32 * 33);
                xi += kb[cc_u * 33 + b_u];
                xf += kb[(8 + cc_u) * 33 + b_u];
                xg += kb[(16 + cc_u) * 33 + b_u];
                xo += kb[(24 + cc_u) * 33 + b_u];
            }
            float ig = 1.f / (1.f + __expf(-xi));
            float fg = 1.f / (1.f + __expf(-xf));
            float gg = tanhf(xg);
            float og = 1.f / (1.f + __expf(-xo));
            float c  = fg * csl[cc_u * 32 + b_u] + ig * gg;
            csl[cc_u * 32 + b_u] = c;
            float h  = og * tanhf(c);

            out[(size_t)t * (BATCH * 1024) + (size_t)b_u * 1024 + dir * DIM + j0 + cc_u] = h;

            // stage split h into smem for coalesced store
            __half hh = __float2half_rn(h);
            hst_hi[b_u * 8 + cc_u] = hh;
            hst_lo[b_u * 8 + cc_u] = __float2half_rn(h - __half2float(hh));

            if (s == T_LEN - 1) {
                hout[((size_t)dir * BATCH + b_u) * DIM + j0 + cc_u] = h;
                cout[((size_t)dir * BATCH + b_u) * DIM + j0 + cc_u] = c;
            }
        }
        __syncthreads();

        // coalesced h history store: warp 0 = hi, warp 1 = lo (16B per lane)
        {
            const size_t hbase = (size_t)(dir * T_LEN + t) * (BATCH * DIM) + j0;
            if (wid == 0) {
                uint4 v = *(uint4*)&hst_hi[lane * 8];
                *(uint4*)(g_hhi + hbase + (size_t)lane * DIM) = v;
            } else if (wid == 1) {
                uint4 v = *(uint4*)&hst_lo[lane * 8];
                *(uint4*)(g_hlo + hbase + (size_t)lane * DIM) = v;
            }
        }
        __syncthreads();

        if (tid == 0) {
            __threadfence();
            *(volatile int*)&g_flags[(dir * T_LEN + s) * NCTA_DIR + slot] = 1;
        }
    }
}

// ---------------------------------------------------------------------------
// launch
// ---------------------------------------------------------------------------
extern "C" void kernel_launch(void* const* d_in, const int* in_sizes, int n_in,
                              void* d_out, int out_size)
{
    (void)in_sizes; (void)n_in; (void)out_size;
    const float* x   = (const float*)d_in[0];
    const float* h0  = (const float*)d_in[1];
    const float* c0  = (const float*)d_in[2];
    const float* Wih = (const float*)d_in[3];
    const float* bih = (const float*)d_in[4];
    const float* Whh = (const float*)d_in[5];
    const float* bhh = (const float*)d_in[6];

    float* out  = (float*)d_out;
    float* hout = out + (size_t)T_LEN * BATCH * 1024;
    float* cout = hout + (size_t)2 * BATCH * DIM;

    init_flags_kernel<<<(2 * T_LEN * NCTA_DIR + 255) / 256, 256>>>();

    __half *xhi, *xlo, *wf;
    cudaGetSymbolAddress((void**)&xhi, g_xhi);
    cudaGetSymbolAddress((void**)&xlo, g_xlo);
    cudaGetSymbolAddress((void**)&wf,  g_wf);
    {
        int nx = 16384 * 512;
        splith_kernel<<<nx / 4 / 256, 256>>>(x, xhi, xlo, nx);
        int nw = 4096 * 512;
        cvt_kernel<<<nw / 4 / 256, 256>>>(Wih, wf, nw);
    }

    {
        size_t smem = 4 * STAGE1;
        cudaFuncSetAttribute(xpre_mma_kernel,
                             cudaFuncAttributeMaxDynamicSharedMemorySize, (int)smem);
        dim3 grid(4096 / 128, 16384 / 128);
        xpre_mma_kernel<<<grid, 256, smem>>>(bih, bhh);
    }

    {
        cudaFuncSetAttribute(lstm_rec_mma_kernel,
                             cudaFuncAttributeMaxDynamicSharedMemorySize, SMEM2_TOTAL);
        lstm_rec_mma_kernel<<<2 * NCTA_DIR, 256, SMEM2_TOTAL>>>(h0, c0, Whh, out, hout, cout);
    }
}

// round 9
// speedup vs baseline: 1.3341x; 1.3317x over previous
#include <cuda_runtime.h>
#include <cuda_fp16.h>
#include <cstdint>

// Problem constants
#define T_LEN 512
#define BATCH 32
#define DIM   512   // D == H
#define G4    2048  // 4*H
#define NCTA_DIR 64 // recurrence CTAs per direction (8 H-cols each)

// Scratch
__device__ float g_xpre[(size_t)2 * T_LEN * G4 * BATCH]; // [dir][t][g][b]
__device__ int   g_sync[2 * T_LEN];                      // per-(dir,step) arrival counters

// fp16 split scratch for phase-1 GEMM: x hi/lo, W single
__device__ __half g_xhi[(size_t)16384 * 512];
__device__ __half g_xlo[(size_t)16384 * 512];
__device__ __half g_wf [(size_t)4096 * 512];

// h history in split fp16: [dir][t][b][512]
__device__ __half g_hhi[(size_t)2 * T_LEN * BATCH * DIM];
__device__ __half g_hlo[(size_t)2 * T_LEN * BATCH * DIM];

__device__ __forceinline__ uint32_t smem_to_u32(const void* p) {
    uint32_t a;
    asm("{ .reg .u64 t; cvta.to.shared.u64 t, %1; cvt.u32.u64 %0, t; }" : "=r"(a) : "l"(p));
    return a;
}

#define CP_ASYNC16(dst, src) \
    asm volatile("cp.async.cg.shared.global [%0], [%1], 16;" :: "r"(dst), "l"(src) : "memory")
#define CP_COMMIT() asm volatile("cp.async.commit_group;" ::: "memory")
#define CP_WAIT2()  asm volatile("cp.async.wait_group 2;" ::: "memory")
#define CP_WAIT0()  asm volatile("cp.async.wait_group 0;" ::: "memory")

#define LDMATRIX_X4(r0, r1, r2, r3, addr) \
    asm volatile("ldmatrix.sync.aligned.m8n8.x4.shared.b16 {%0,%1,%2,%3}, [%4];" \
        : "=r"(r0), "=r"(r1), "=r"(r2), "=r"(r3) : "r"(addr))
#define LDMATRIX_X2(r0, r1, addr) \
    asm volatile("ldmatrix.sync.aligned.m8n8.x2.shared.b16 {%0,%1}, [%2];" \
        : "=r"(r0), "=r"(r1) : "r"(addr))

#define MMA_F16(d, a, b) \
    asm volatile("mma.sync.aligned.m16n8k16.row.col.f32.f16.f16.f32 " \
        "{%0,%1,%2,%3}, {%4,%5,%6,%7}, {%8,%9}, {%0,%1,%2,%3};" \
        : "+f"((d)[0]), "+f"((d)[1]), "+f"((d)[2]), "+f"((d)[3]) \
        : "r"((a)[0]), "r"((a)[1]), "r"((a)[2]), "r"((a)[3]), "r"((b)[0]), "r"((b)[1]))

// pack two fp32 into f16x2 (low half = a, high half = b)
__device__ __forceinline__ uint32_t pack_f16(float a, float b) {
    uint32_t r;
    asm("cvt.rn.f16x2.f32 %0, %1, %2;" : "=r"(r) : "f"(b), "f"(a));
    return r;
}

// ---------------------------------------------------------------------------
__global__ void init_sync_kernel() {
    int i = blockIdx.x * blockDim.x + threadIdx.x;
    if (i < 2 * T_LEN) g_sync[i] = 0;
}

// fp32 -> fp16 hi/lo split
__global__ void splith_kernel(const float* __restrict__ src,
                              __half* __restrict__ hi,
                              __half* __restrict__ lo, int n) {
    int i = (blockIdx.x * blockDim.x + threadIdx.x) * 4;
    if (i >= n) return;
    float4 v = *(const float4*)(src + i);
    float vs[4] = {v.x, v.y, v.z, v.w};
#pragma unroll
    for (int j = 0; j < 4; j++) {
        __half h = __float2half_rn(vs[j]);
        hi[i + j] = h;
        lo[i + j] = __float2half_rn(vs[j] - __half2float(h));
    }
}

// fp32 -> fp16 single
__global__ void cvt_kernel(const float* __restrict__ src,
                           __half* __restrict__ dst, int n) {
    int i = (blockIdx.x * blockDim.x + threadIdx.x) * 4;
    if (i >= n) return;
    float4 v = *(const float4*)(src + i);
    dst[i + 0] = __float2half_rn(v.x);
    dst[i + 1] = __float2half_rn(v.y);
    dst[i + 2] = __float2half_rn(v.z);
    dst[i + 3] = __float2half_rn(v.w);
}

// ---------------------------------------------------------------------------
// Phase 1: HMMA fp16 2-pass GEMM for x_pre (measured 556us, unchanged).
// ---------------------------------------------------------------------------
#define KC1 32
#define RPAD1 40
#define ARR1 (128 * RPAD1 * 2)
#define STAGE1 (3 * ARR1)
#define NCHUNK1 16

__global__ __launch_bounds__(256, 1)
void xpre_mma_kernel(const float* __restrict__ bih, const float* __restrict__ bhh)
{
    extern __shared__ char smem[];
    const uint32_t sb = smem_to_u32(smem);

    const int tid  = threadIdx.x;
    const int wid  = tid >> 5;
    const int lane = tid & 31;
    const int g0   = blockIdx.x * 128;
    const int m0   = blockIdx.y * 128;
    const int wg   = wid >> 1;
    const int wm   = wid & 1;

    const int grp = lane >> 2;
    const int tig = lane & 3;

    const int lrow = tid >> 1;
    const __half* gsrc[3] = {
        g_wf  + (size_t)(g0 + lrow) * 512,
        g_xhi + (size_t)(m0 + lrow) * 512,
        g_xlo + (size_t)(m0 + lrow) * 512
    };

    auto issue_chunk = [&](int kc) {
        const uint32_t stb = sb + (kc & 3) * STAGE1;
#pragma unroll
        for (int arr = 0; arr < 3; arr++) {
#pragma unroll
            for (int i = 0; i < 2; i++) {
                int seg = (tid & 1) * 2 + i;
                CP_ASYNC16(stb + arr * ARR1 + lrow * (RPAD1 * 2) + seg * 16,
                           gsrc[arr] + kc * KC1 + seg * 8);
            }
        }
        CP_COMMIT();
    };

    float acc[2][8][4];
#pragma unroll
    for (int mt = 0; mt < 2; mt++)
#pragma unroll
        for (int nt = 0; nt < 8; nt++)
#pragma unroll
            for (int r = 0; r < 4; r++) acc[mt][nt][r] = 0.f;

    issue_chunk(0);
    issue_chunk(1);
    issue_chunk(2);

    const uint32_t lm_row = (uint32_t)(lane & 15);
    const uint32_t lm_colb = (uint32_t)(lane >> 4) * 16;

    for (int kc = 0; kc < NCHUNK1; kc++) {
        const uint32_t stb = sb + (kc & 3) * STAGE1;
        CP_WAIT2();
        __syncthreads();

        const uint32_t AF  = stb;
        const uint32_t BHI = stb + ARR1;
        const uint32_t BLO = stb + 2 * ARR1;

#pragma unroll
        for (int kk = 0; kk < 2; kk++) {
            const uint32_t kb = lm_colb + kk * 32;

            uint32_t af[2][4], bb[4][4];
#pragma unroll
            for (int mt = 0; mt < 2; mt++) {
                uint32_t aoff = (wg * 32 + mt * 16 + lm_row) * (RPAD1 * 2) + kb;
                LDMATRIX_X4(af[mt][0], af[mt][1], af[mt][2], af[mt][3], AF + aoff);
            }
#pragma unroll
            for (int nt2 = 0; nt2 < 4; nt2++) {
                uint32_t boff = (wm * 64 + nt2 * 16 + lm_row) * (RPAD1 * 2) + kb;
                LDMATRIX_X4(bb[nt2][0], bb[nt2][1], bb[nt2][2], bb[nt2][3], BHI + boff);
            }
#pragma unroll
            for (int mt = 0; mt < 2; mt++)
#pragma unroll
                for (int nt = 0; nt < 8; nt++) {
                    uint32_t bfrag[2] = { bb[nt >> 1][nt & 1], bb[nt >> 1][(nt & 1) + 2] };
                    MMA_F16(acc[mt][nt], af[mt], bfrag);
                }
#pragma unroll
            for (int nt2 = 0; nt2 < 4; nt2++) {
                uint32_t boff = (wm * 64 + nt2 * 16 + lm_row) * (RPAD1 * 2) + kb;
                LDMATRIX_X4(bb[nt2][0], bb[nt2][1], bb[nt2][2], bb[nt2][3], BLO + boff);
            }
#pragma unroll
            for (int mt = 0; mt < 2; mt++)
#pragma unroll
                for (int nt = 0; nt < 8; nt++) {
                    uint32_t bfrag[2] = { bb[nt >> 1][nt & 1], bb[nt >> 1][(nt & 1) + 2] };
                    MMA_F16(acc[mt][nt], af[mt], bfrag);
                }
        }
        __syncthreads();
        if (kc + 3 < NCHUNK1) issue_chunk(kc + 3);
    }

    float bias[2][2];
    float* rowp[2][2];
#pragma unroll
    for (int mt = 0; mt < 2; mt++)
#pragma unroll
        for (int hf = 0; hf < 2; hf++) {
            int g = g0 + wg * 32 + mt * 16 + hf * 8 + grp;
            bias[mt][hf] = bih[g] + bhh[g];
            int d = g >> 11, gp = g & 2047;
            rowp[mt][hf] = g_xpre + ((size_t)d * T_LEN) * (G4 * BATCH) + (size_t)gp * BATCH;
        }
#pragma unroll
    for (int mt = 0; mt < 2; mt++)
#pragma unroll
        for (int nt = 0; nt < 8; nt++) {
            int m = m0 + wm * 64 + nt * 8 + 2 * tig;
            int t = m >> 5, b = m & 31;
            size_t toff = (size_t)t * (G4 * BATCH) + b;
            float2 v0 = { acc[mt][nt][0] + bias[mt][0], acc[mt][nt][1] + bias[mt][0] };
            float2 v1 = { acc[mt][nt][2] + bias[mt][1], acc[mt][nt][3] + bias[mt][1] };
            *(float2*)(rowp[mt][0] + toff) = v0;
            *(float2*)(rowp[mt][1] + toff) = v1;
        }
}

// ---------------------------------------------------------------------------
// Phase 2 v5: R5 skeleton (single atomic counter, tid0 poll, direct h stores)
//   + fp16 2-pass MMA (W single fp16, h hi/lo).
//   Warp = (mhalf, kgroup): 16 batches x 32 gate rows x 128 k-slice.
//   Release reordered: h history stores -> flag; fp32 out stores after.
// ---------------------------------------------------------------------------
#define KPAD 520
#define WF_OFF  0
#define HHI_OFF (32 * KPAD * 2)            // 33280
#define HLO_OFF (2 * 32 * KPAD * 2)        // 66560
#define KGB_OFF (3 * 32 * KPAD * 2)        // 99840
#define XPS_OFF (KGB_OFF + 4 * 32 * 33 * 4)// 116736
#define CSL_OFF (XPS_OFF + 32 * 36 * 4)    // 121344
#define SMEM2_TOTAL (CSL_OFF + 8 * 32 * 4)

__global__ __launch_bounds__(256, 1)
void lstm_rec_mma_kernel(const float* __restrict__ h0,
                         const float* __restrict__ c0,
                         const float* __restrict__ Whh,
                         float* __restrict__ out,
                         float* __restrict__ hout,
                         float* __restrict__ cout)
{
    extern __shared__ char smraw[];
    const uint32_t sb = smem_to_u32(smraw);
    float* kgb = (float*)(smraw + KGB_OFF);
    float* xps = (float*)(smraw + XPS_OFF);
    float* csl = (float*)(smraw + CSL_OFF);
    uint32_t* Wf32  = (uint32_t*)(smraw + WF_OFF);
    uint32_t* Hhi32 = (uint32_t*)(smraw + HHI_OFF);
    uint32_t* Hlo32 = (uint32_t*)(smraw + HLO_OFF);

    const int cta  = blockIdx.x;
    const int dir  = cta >> 6;
    const int j0   = (cta & (NCTA_DIR - 1)) * 8;
    const int tid  = threadIdx.x;
    const int wid  = tid >> 5;
    const int lane = tid & 31;
    const int mhalf = wid >> 2;
    const int kg    = wid & 3;
    const int m0w   = mhalf * 16;

    // ---- convert W_hh slice into smem fp16 ----
    {
        int lr = tid >> 3, seg = tid & 7;
        int gr = (lr >> 3) * DIM + j0 + (lr & 7);
        const float4* src = (const float4*)(Whh + ((size_t)dir * G4 + gr) * DIM + seg * 64);
#pragma unroll
        for (int i = 0; i < 16; i++) {
            float4 v = src[i];
            int k = seg * 64 + i * 4;
            int u = (lr * KPAD + k) >> 1;
            Wf32[u]     = pack_f16(v.x, v.y);
            Wf32[u + 1] = pack_f16(v.z, v.w);
        }
    }
    {
        int cc = tid >> 5, b = tid & 31;
        csl[cc * 32 + b] = c0[((size_t)dir * BATCH + b) * DIM + j0 + cc];
    }
    __syncthreads();

    // ---- preload W fragments (step-invariant): bw[nt][ks][2] ----
    uint32_t bw[4][8][2];
    {
        const uint32_t brow = (uint32_t)(lane & 7);
        const uint32_t bcol = (uint32_t)((lane >> 3) & 1) * 16;
#pragma unroll
        for (int nt = 0; nt < 4; nt++)
#pragma unroll
            for (int ks = 0; ks < 8; ks++) {
                uint32_t off = (nt * 8 + brow) * (KPAD * 2) + kg * 256 + ks * 32 + bcol;
                LDMATRIX_X2(bw[nt][ks][0], bw[nt][ks][1], sb + WF_OFF + off);
            }
    }

    const uint32_t arow_off = (uint32_t)(m0w + (lane & 15)) * (KPAD * 2)
                            + (uint32_t)kg * 256 + (uint32_t)(lane >> 4) * 16;

    const int cc_u = tid >> 5;
    const int b_u  = tid & 31;
    const int grp  = lane >> 2;
    const int tig  = lane & 3;

    for (int s = 0; s < T_LEN; s++) {
        const int t = dir ? (T_LEN - 1 - s) : s;

        // prefetch x_pre slice (independent of h) BEFORE the flag wait
        {
            int lr = tid >> 3, seg = tid & 7;
            int gp = (lr >> 3) * DIM + j0 + (lr & 7);
            const float* src = g_xpre + (size_t)dir * ((size_t)T_LEN * G4 * BATCH)
                             + (size_t)t * (G4 * BATCH) + (size_t)gp * BATCH + seg * 4;
            CP_ASYNC16(sb + XPS_OFF + (uint32_t)(lr * 144 + seg * 16), src);
            CP_COMMIT();
        }

        if (s == 0) {
            const float4* h0p = (const float4*)(h0 + (size_t)dir * BATCH * DIM);
#pragma unroll
            for (int it = 0; it < 16; it++) {
                int idx = tid + it * 256;
                int b = idx >> 7, c4 = (idx & 127) * 4;
                float4 v = h0p[idx];
                float f0 = __half2float(__float2half_rn(v.x));
                float f1 = __half2float(__float2half_rn(v.y));
                float f2 = __half2float(__float2half_rn(v.z));
                float f3 = __half2float(__float2half_rn(v.w));
                int u = (b * KPAD + c4) >> 1;
                Hhi32[u]     = pack_f16(f0, f1);
                Hhi32[u + 1] = pack_f16(f2, f3);
                Hlo32[u]     = pack_f16(v.x - f0, v.y - f1);
                Hlo32[u + 1] = pack_f16(v.z - f2, v.w - f3);
            }
            CP_WAIT0();
            __syncthreads();
        } else {
            if (tid == 0) {
                volatile int* f = &g_sync[dir * T_LEN + (s - 1)];
                while (*f < NCTA_DIR) { }
                __threadfence();
            }
            __syncthreads();
            // warp-local h cp.async: 16 batches x 128 k, hi+lo
            const int tp = dir ? (t + 1) : (t - 1);
            const __half* hh = g_hhi + (size_t)(dir * T_LEN + tp) * (BATCH * DIM);
            const __half* hl = g_hlo + (size_t)(dir * T_LEN + tp) * (BATCH * DIM);
#pragma unroll
            for (int it = 0; it < 8; it++) {
                int u = lane + it * 32;
                int r = u >> 4, sg = u & 15;
                int row = m0w + r;
                size_t goff = (size_t)row * DIM + kg * 128 + sg * 8;
                uint32_t doff = (uint32_t)(row * KPAD + kg * 128 + sg * 8) * 2;
                CP_ASYNC16(sb + HHI_OFF + doff, hh + goff);
                CP_ASYNC16(sb + HLO_OFF + doff, hl + goff);
            }
            CP_COMMIT();
            CP_WAIT0();   // per-warp: no CTA barrier before MMA
        }

        // ---- MMA: (h_hi + h_lo) @ W^T, 2 passes ----
        float acc[4][4];
#pragma unroll
        for (int nt = 0; nt < 4; nt++)
#pragma unroll
            for (int r = 0; r < 4; r++) acc[nt][r] = 0.f;

#pragma unroll
        for (int ks = 0; ks < 8; ks++) {
            uint32_t a_h[4], a_l[4];
            LDMATRIX_X4(a_h[0], a_h[1], a_h[2], a_h[3], sb + HHI_OFF + arow_off + ks * 32);
            LDMATRIX_X4(a_l[0], a_l[1], a_l[2], a_l[3], sb + HLO_OFF + arow_off + ks * 32);
#pragma unroll
            for (int nt = 0; nt < 4; nt++) {
                MMA_F16(acc[nt], a_h, bw[nt][ks]);
                MMA_F16(acc[nt], a_l, bw[nt][ks]);
            }
        }

        // scatter partials to kgb[kg][n][b]
        {
            float* kb = kgb + kg * (32 * 33);
            int b1 = m0w + grp, b2 = b1 + 8;
#pragma unroll
            for (int nt = 0; nt < 4; nt++) {
                int na = nt * 8 + 2 * tig;
                kb[na * 33 + b1]       = acc[nt][0];
                kb[(na + 1) * 33 + b1] = acc[nt][1];
                kb[na * 33 + b2]       = acc[nt][2];
                kb[(na + 1) * 33 + b2] = acc[nt][3];
            }
        }
        __syncthreads();

        // ---- LSTM update: thread -> (cc_u, b_u); reduce 4 k-partials ----
        float h_val, c_val;
        {
            float xi = xps[cc_u * 36 + b_u];
            float xf = xps[(8 + cc_u) * 36 + b_u];
            float xg = xps[(16 + cc_u) * 36 + b_u];
            float xo = xps[(24 + cc_u) * 36 + b_u];
#pragma unroll
            for (int k = 0; k < 4; k++) {
                const float* kb = kgb + k * (32 * 33);
                xi += kb[cc_u * 33 + b_u];
                xf += kb[(8 + cc_u) * 33 + b_u];
                xg += kb[(16 + cc_u) * 33 + b_u];
                xo += kb[(24 + cc_u) * 33 + b_u];
            }
            float ig = 1.f / (1.f + __expf(-xi));
            float fg = 1.f / (1.f + __expf(-xf));
            float gg = tanhf(xg);
            float og = 1.f / (1.f + __expf(-xo));
            c_val = fg * csl[cc_u * 32 + b_u] + ig * gg;
            csl[cc_u * 32 + b_u] = c_val;
            h_val = og * tanhf(c_val);

            // h history (protocol data) first — release depends only on this
            __half hh = __float2half_rn(h_val);
            __half hl = __float2half_rn(h_val - __half2float(hh));
            size_t hoff = (size_t)(dir * T_LEN + t) * (BATCH * DIM) + (size_t)b_u * DIM + j0 + cc_u;
            g_hhi[hoff] = hh;
            g_hlo[hoff] = hl;
        }

        __syncthreads();
        if (tid == 0) {
            __threadfence();
            atomicAdd(&g_sync[dir * T_LEN + s], 1);
        }

        // off-critical-path stores: fp32 output (+ finals on last step)
        out[(size_t)t * (BATCH * 1024) + (size_t)b_u * 1024 + dir * DIM + j0 + cc_u] = h_val;
        if (s == T_LEN - 1) {
            hout[((size_t)dir * BATCH + b_u) * DIM + j0 + cc_u] = h_val;
            cout[((size_t)dir * BATCH + b_u) * DIM + j0 + cc_u] = c_val;
        }
    }
}

// ---------------------------------------------------------------------------
// launch
// ---------------------------------------------------------------------------
extern "C" void kernel_launch(void* const* d_in, const int* in_sizes, int n_in,
                              void* d_out, int out_size)
{
    (void)in_sizes; (void)n_in; (void)out_size;
    const float* x   = (const float*)d_in[0];
    const float* h0  = (const float*)d_in[1];
    const float* c0  = (const float*)d_in[2];
    const float* Wih = (const float*)d_in[3];
    const float* bih = (const float*)d_in[4];
    const float* Whh = (const float*)d_in[5];
    const float* bhh = (const float*)d_in[6];

    float* out  = (float*)d_out;
    float* hout = out + (size_t)T_LEN * BATCH * 1024;
    float* cout = hout + (size_t)2 * BATCH * DIM;

    init_sync_kernel<<<4, 256>>>();

    __half *xhi, *xlo, *wf;
    cudaGetSymbolAddress((void**)&xhi, g_xhi);
    cudaGetSymbolAddress((void**)&xlo, g_xlo);
    cudaGetSymbolAddress((void**)&wf,  g_wf);
    {
        int nx = 16384 * 512;
        splith_kernel<<<nx / 4 / 256, 256>>>(x, xhi, xlo, nx);
        int nw = 4096 * 512;
        cvt_kernel<<<nw / 4 / 256, 256>>>(Wih, wf, nw);
    }

    {
        size_t smem = 4 * STAGE1;
        cudaFuncSetAttribute(xpre_mma_kernel,
                             cudaFuncAttributeMaxDynamicSharedMemorySize, (int)smem);
        dim3 grid(4096 / 128, 16384 / 128);
        xpre_mma_kernel<<<grid, 256, smem>>>(bih, bhh);
    }

    {
        cudaFuncSetAttribute(lstm_rec_mma_kernel,
                             cudaFuncAttributeMaxDynamicSharedMemorySize, SMEM2_TOTAL);
        lstm_rec_mma_kernel<<<2 * NCTA_DIR, 256, SMEM2_TOTAL>>>(h0, c0, Whh, out, hout, cout);
    }
}

// round 10
// speedup vs baseline: 1.6354x; 1.2258x over previous
#include <cuda_runtime.h>
#include <cuda_fp16.h>
#include <cstdint>

// Problem constants
#define T_LEN 512
#define BATCH 32
#define DIM   512   // D == H
#define G4    2048  // 4*H
#define NCTA_DIR 64 // recurrence CTAs per direction (8 H-cols each)

// Scratch
__device__ float g_xpre[(size_t)2 * T_LEN * G4 * BATCH]; // [dir][t][g][b]
__device__ int   g_sync[2 * T_LEN];                      // per-(dir,step) arrival counters

// fp16 split scratch for phase-1 GEMM: x hi/lo, W single
__device__ __half g_xhi[(size_t)16384 * 512];
__device__ __half g_xlo[(size_t)16384 * 512];
__device__ __half g_wf [(size_t)4096 * 512];

// h history: SINGLE fp16 plane [dir][t][b][512]
__device__ __half g_hf[(size_t)2 * T_LEN * BATCH * DIM];

__device__ __forceinline__ uint32_t smem_to_u32(const void* p) {
    uint32_t a;
    asm("{ .reg .u64 t; cvta.to.shared.u64 t, %1; cvt.u32.u64 %0, t; }" : "=r"(a) : "l"(p));
    return a;
}

#define CP_ASYNC16(dst, src) \
    asm volatile("cp.async.cg.shared.global [%0], [%1], 16;" :: "r"(dst), "l"(src) : "memory")
#define CP_COMMIT() asm volatile("cp.async.commit_group;" ::: "memory")
#define CP_WAIT2()  asm volatile("cp.async.wait_group 2;" ::: "memory")
#define CP_WAIT0()  asm volatile("cp.async.wait_group 0;" ::: "memory")

#define LDMATRIX_X4(r0, r1, r2, r3, addr) \
    asm volatile("ldmatrix.sync.aligned.m8n8.x4.shared.b16 {%0,%1,%2,%3}, [%4];" \
        : "=r"(r0), "=r"(r1), "=r"(r2), "=r"(r3) : "r"(addr))
#define LDMATRIX_X2(r0, r1, addr) \
    asm volatile("ldmatrix.sync.aligned.m8n8.x2.shared.b16 {%0,%1}, [%2];" \
        : "=r"(r0), "=r"(r1) : "r"(addr))

#define MMA_F16(d, a, b) \
    asm volatile("mma.sync.aligned.m16n8k16.row.col.f32.f16.f16.f32 " \
        "{%0,%1,%2,%3}, {%4,%5,%6,%7}, {%8,%9}, {%0,%1,%2,%3};" \
        : "+f"((d)[0]), "+f"((d)[1]), "+f"((d)[2]), "+f"((d)[3]) \
        : "r"((a)[0]), "r"((a)[1]), "r"((a)[2]), "r"((a)[3]), "r"((b)[0]), "r"((b)[1]))

// pack two fp32 into f16x2 (low half = a, high half = b)
__device__ __forceinline__ uint32_t pack_f16(float a, float b) {
    uint32_t r;
    asm("cvt.rn.f16x2.f32 %0, %1, %2;" : "=r"(r) : "f"(b), "f"(a));
    return r;
}

// ---------------------------------------------------------------------------
__global__ void init_sync_kernel() {
    int i = blockIdx.x * blockDim.x + threadIdx.x;
    if (i < 2 * T_LEN) g_sync[i] = 0;
}

// fp32 -> fp16 hi/lo split
__global__ void splith_kernel(const float* __restrict__ src,
                              __half* __restrict__ hi,
                              __half* __restrict__ lo, int n) {
    int i = (blockIdx.x * blockDim.x + threadIdx.x) * 4;
    if (i >= n) return;
    float4 v = *(const float4*)(src + i);
    float vs[4] = {v.x, v.y, v.z, v.w};
#pragma unroll
    for (int j = 0; j < 4; j++) {
        __half h = __float2half_rn(vs[j]);
        hi[i + j] = h;
        lo[i + j] = __float2half_rn(vs[j] - __half2float(h));
    }
}

// fp32 -> fp16 single
__global__ void cvt_kernel(const float* __restrict__ src,
                           __half* __restrict__ dst, int n) {
    int i = (blockIdx.x * blockDim.x + threadIdx.x) * 4;
    if (i >= n) return;
    float4 v = *(const float4*)(src + i);
    dst[i + 0] = __float2half_rn(v.x);
    dst[i + 1] = __float2half_rn(v.y);
    dst[i + 2] = __float2half_rn(v.z);
    dst[i + 3] = __float2half_rn(v.w);
}

// ---------------------------------------------------------------------------
// Phase 1: HMMA fp16 2-pass GEMM for x_pre (measured 555us, unchanged).
// ---------------------------------------------------------------------------
#define KC1 32
#define RPAD1 40
#define ARR1 (128 * RPAD1 * 2)
#define STAGE1 (3 * ARR1)
#define NCHUNK1 16

__global__ __launch_bounds__(256, 1)
void xpre_mma_kernel(const float* __restrict__ bih, const float* __restrict__ bhh)
{
    extern __shared__ char smem[];
    const uint32_t sb = smem_to_u32(smem);

    const int tid  = threadIdx.x;
    const int wid  = tid >> 5;
    const int lane = tid & 31;
    const int g0   = blockIdx.x * 128;
    const int m0   = blockIdx.y * 128;
    const int wg   = wid >> 1;
    const int wm   = wid & 1;

    const int grp = lane >> 2;
    const int tig = lane & 3;

    const int lrow = tid >> 1;
    const __half* gsrc[3] = {
        g_wf  + (size_t)(g0 + lrow) * 512,
        g_xhi + (size_t)(m0 + lrow) * 512,
        g_xlo + (size_t)(m0 + lrow) * 512
    };

    auto issue_chunk = [&](int kc) {
        const uint32_t stb = sb + (kc & 3) * STAGE1;
#pragma unroll
        for (int arr = 0; arr < 3; arr++) {
#pragma unroll
            for (int i = 0; i < 2; i++) {
                int seg = (tid & 1) * 2 + i;
                CP_ASYNC16(stb + arr * ARR1 + lrow * (RPAD1 * 2) + seg * 16,
                           gsrc[arr] + kc * KC1 + seg * 8);
            }
        }
        CP_COMMIT();
    };

    float acc[2][8][4];
#pragma unroll
    for (int mt = 0; mt < 2; mt++)
#pragma unroll
        for (int nt = 0; nt < 8; nt++)
#pragma unroll
            for (int r = 0; r < 4; r++) acc[mt][nt][r] = 0.f;

    issue_chunk(0);
    issue_chunk(1);
    issue_chunk(2);

    const uint32_t lm_row = (uint32_t)(lane & 15);
    const uint32_t lm_colb = (uint32_t)(lane >> 4) * 16;

    for (int kc = 0; kc < NCHUNK1; kc++) {
        const uint32_t stb = sb + (kc & 3) * STAGE1;
        CP_WAIT2();
        __syncthreads();

        const uint32_t AF  = stb;
        const uint32_t BHI = stb + ARR1;
        const uint32_t BLO = stb + 2 * ARR1;

#pragma unroll
        for (int kk = 0; kk < 2; kk++) {
            const uint32_t kb = lm_colb + kk * 32;

            uint32_t af[2][4], bb[4][4];
#pragma unroll
            for (int mt = 0; mt < 2; mt++) {
                uint32_t aoff = (wg * 32 + mt * 16 + lm_row) * (RPAD1 * 2) + kb;
                LDMATRIX_X4(af[mt][0], af[mt][1], af[mt][2], af[mt][3], AF + aoff);
            }
#pragma unroll
            for (int nt2 = 0; nt2 < 4; nt2++) {
                uint32_t boff = (wm * 64 + nt2 * 16 + lm_row) * (RPAD1 * 2) + kb;
                LDMATRIX_X4(bb[nt2][0], bb[nt2][1], bb[nt2][2], bb[nt2][3], BHI + boff);
            }
#pragma unroll
            for (int mt = 0; mt < 2; mt++)
#pragma unroll
                for (int nt = 0; nt < 8; nt++) {
                    uint32_t bfrag[2] = { bb[nt >> 1][nt & 1], bb[nt >> 1][(nt & 1) + 2] };
                    MMA_F16(acc[mt][nt], af[mt], bfrag);
                }
#pragma unroll
            for (int nt2 = 0; nt2 < 4; nt2++) {
                uint32_t boff = (wm * 64 + nt2 * 16 + lm_row) * (RPAD1 * 2) + kb;
                LDMATRIX_X4(bb[nt2][0], bb[nt2][1], bb[nt2][2], bb[nt2][3], BLO + boff);
            }
#pragma unroll
            for (int mt = 0; mt < 2; mt++)
#pragma unroll
                for (int nt = 0; nt < 8; nt++) {
                    uint32_t bfrag[2] = { bb[nt >> 1][nt & 1], bb[nt >> 1][(nt & 1) + 2] };
                    MMA_F16(acc[mt][nt], af[mt], bfrag);
                }
        }
        __syncthreads();
        if (kc + 3 < NCHUNK1) issue_chunk(kc + 3);
    }

    float bias[2][2];
    float* rowp[2][2];
#pragma unroll
    for (int mt = 0; mt < 2; mt++)
#pragma unroll
        for (int hf = 0; hf < 2; hf++) {
            int g = g0 + wg * 32 + mt * 16 + hf * 8 + grp;
            bias[mt][hf] = bih[g] + bhh[g];
            int d = g >> 11, gp = g & 2047;
            rowp[mt][hf] = g_xpre + ((size_t)d * T_LEN) * (G4 * BATCH) + (size_t)gp * BATCH;
        }
#pragma unroll
    for (int mt = 0; mt < 2; mt++)
#pragma unroll
        for (int nt = 0; nt < 8; nt++) {
            int m = m0 + wm * 64 + nt * 8 + 2 * tig;
            int t = m >> 5, b = m & 31;
            size_t toff = (size_t)t * (G4 * BATCH) + b;
            float2 v0 = { acc[mt][nt][0] + bias[mt][0], acc[mt][nt][1] + bias[mt][0] };
            float2 v1 = { acc[mt][nt][2] + bias[mt][1], acc[mt][nt][3] + bias[mt][1] };
            *(float2*)(rowp[mt][0] + toff) = v0;
            *(float2*)(rowp[mt][1] + toff) = v1;
        }
}

// ---------------------------------------------------------------------------
// Phase 2 v6: h history single fp16 (halved L2 broadcast), W_hh exact hi/lo
//   in SMEM + 128 preloaded regs, 2 MMA passes. Sync identical to R9.
// ---------------------------------------------------------------------------
#define KPAD 520
#define WHI_OFF 0
#define WLO_OFF (32 * KPAD * 2)            // 33280
#define HF_OFF  (2 * 32 * KPAD * 2)        // 66560
#define KGB_OFF (3 * 32 * KPAD * 2)        // 99840
#define XPS_OFF (KGB_OFF + 4 * 32 * 33 * 4)// 116736
#define CSL_OFF (XPS_OFF + 32 * 36 * 4)    // 121344
#define SMEM2_TOTAL (CSL_OFF + 8 * 32 * 4)

__global__ __launch_bounds__(256, 1)
void lstm_rec_mma_kernel(const float* __restrict__ h0,
                         const float* __restrict__ c0,
                         const float* __restrict__ Whh,
                         float* __restrict__ out,
                         float* __restrict__ hout,
                         float* __restrict__ cout)
{
    extern __shared__ char smraw[];
    const uint32_t sb = smem_to_u32(smraw);
    float* kgb = (float*)(smraw + KGB_OFF);
    float* xps = (float*)(smraw + XPS_OFF);
    float* csl = (float*)(smraw + CSL_OFF);
    uint32_t* Whi32 = (uint32_t*)(smraw + WHI_OFF);
    uint32_t* Wlo32 = (uint32_t*)(smraw + WLO_OFF);
    uint32_t* Hf32  = (uint32_t*)(smraw + HF_OFF);

    const int cta  = blockIdx.x;
    const int dir  = cta >> 6;
    const int j0   = (cta & (NCTA_DIR - 1)) * 8;
    const int tid  = threadIdx.x;
    const int wid  = tid >> 5;
    const int lane = tid & 31;
    const int mhalf = wid >> 2;
    const int kg    = wid & 3;
    const int m0w   = mhalf * 16;

    // ---- load & split W_hh slice into smem fp16 hi/lo ----
    {
        int lr = tid >> 3, seg = tid & 7;
        int gr = (lr >> 3) * DIM + j0 + (lr & 7);
        const float4* src = (const float4*)(Whh + ((size_t)dir * G4 + gr) * DIM + seg * 64);
#pragma unroll
        for (int i = 0; i < 16; i++) {
            float4 v = src[i];
            int k = seg * 64 + i * 4;
            float f0 = __half2float(__float2half_rn(v.x));
            float f1 = __half2float(__float2half_rn(v.y));
            float f2 = __half2float(__float2half_rn(v.z));
            float f3 = __half2float(__float2half_rn(v.w));
            int u = (lr * KPAD + k) >> 1;
            Whi32[u]     = pack_f16(f0, f1);
            Whi32[u + 1] = pack_f16(f2, f3);
            Wlo32[u]     = pack_f16(v.x - f0, v.y - f1);
            Wlo32[u + 1] = pack_f16(v.z - f2, v.w - f3);
        }
    }
    {
        int cc = tid >> 5, b = tid & 31;
        csl[cc * 32 + b] = c0[((size_t)dir * BATCH + b) * DIM + j0 + cc];
    }
    __syncthreads();

    // ---- preload W fragments (step-invariant): bwh/bwl[nt][ks][2] ----
    uint32_t bwh[4][8][2], bwl[4][8][2];
    {
        const uint32_t brow = (uint32_t)(lane & 7);
        const uint32_t bcol = (uint32_t)((lane >> 3) & 1) * 16;
#pragma unroll
        for (int nt = 0; nt < 4; nt++)
#pragma unroll
            for (int ks = 0; ks < 8; ks++) {
                uint32_t off = (nt * 8 + brow) * (KPAD * 2) + kg * 256 + ks * 32 + bcol;
                LDMATRIX_X2(bwh[nt][ks][0], bwh[nt][ks][1], sb + WHI_OFF + off);
                LDMATRIX_X2(bwl[nt][ks][0], bwl[nt][ks][1], sb + WLO_OFF + off);
            }
    }

    const uint32_t arow_off = (uint32_t)(m0w + (lane & 15)) * (KPAD * 2)
                            + (uint32_t)kg * 256 + (uint32_t)(lane >> 4) * 16;

    const int cc_u = tid >> 5;
    const int b_u  = tid & 31;
    const int grp  = lane >> 2;
    const int tig  = lane & 3;

    for (int s = 0; s < T_LEN; s++) {
        const int t = dir ? (T_LEN - 1 - s) : s;

        // prefetch x_pre slice (independent of h) BEFORE the flag wait
        {
            int lr = tid >> 3, seg = tid & 7;
            int gp = (lr >> 3) * DIM + j0 + (lr & 7);
            const float* src = g_xpre + (size_t)dir * ((size_t)T_LEN * G4 * BATCH)
                             + (size_t)t * (G4 * BATCH) + (size_t)gp * BATCH + seg * 4;
            CP_ASYNC16(sb + XPS_OFF + (uint32_t)(lr * 144 + seg * 16), src);
            CP_COMMIT();
        }

        if (s == 0) {
            const float4* h0p = (const float4*)(h0 + (size_t)dir * BATCH * DIM);
#pragma unroll
            for (int it = 0; it < 16; it++) {
                int idx = tid + it * 256;
                int b = idx >> 7, c4 = (idx & 127) * 4;
                float4 v = h0p[idx];
                int u = (b * KPAD + c4) >> 1;
                Hf32[u]     = pack_f16(v.x, v.y);
                Hf32[u + 1] = pack_f16(v.z, v.w);
            }
            CP_WAIT0();
            __syncthreads();
        } else {
            if (tid == 0) {
                volatile int* f = &g_sync[dir * T_LEN + (s - 1)];
                while (*f < NCTA_DIR) { }
                __threadfence();
            }
            __syncthreads();
            // warp-local h cp.async: 16 batches x 128 k, single fp16
            const int tp = dir ? (t + 1) : (t - 1);
            const __half* hf = g_hf + (size_t)(dir * T_LEN + tp) * (BATCH * DIM);
#pragma unroll
            for (int it = 0; it < 8; it++) {
                int u = lane + it * 32;
                int r = u >> 4, sg = u & 15;
                int row = m0w + r;
                size_t goff = (size_t)row * DIM + kg * 128 + sg * 8;
                uint32_t doff = (uint32_t)(row * KPAD + kg * 128 + sg * 8) * 2;
                CP_ASYNC16(sb + HF_OFF + doff, hf + goff);
            }
            CP_COMMIT();
            CP_WAIT0();   // per-warp: no CTA barrier before MMA
        }

        // ---- MMA: h @ (W_hi + W_lo)^T, 2 passes, h single fp16 ----
        float acc[4][4];
#pragma unroll
        for (int nt = 0; nt < 4; nt++)
#pragma unroll
            for (int r = 0; r < 4; r++) acc[nt][r] = 0.f;

#pragma unroll
        for (int ks = 0; ks < 8; ks++) {
            uint32_t a_f[4];
            LDMATRIX_X4(a_f[0], a_f[1], a_f[2], a_f[3], sb + HF_OFF + arow_off + ks * 32);
#pragma unroll
            for (int nt = 0; nt < 4; nt++) {
                MMA_F16(acc[nt], a_f, bwh[nt][ks]);
                MMA_F16(acc[nt], a_f, bwl[nt][ks]);
            }
        }

        // scatter partials to kgb[kg][n][b]
        {
            float* kb = kgb + kg * (32 * 33);
            int b1 = m0w + grp, b2 = b1 + 8;
#pragma unroll
            for (int nt = 0; nt < 4; nt++) {
                int na = nt * 8 + 2 * tig;
                kb[na * 33 + b1]       = acc[nt][0];
                kb[(na + 1) * 33 + b1] = acc[nt][1];
                kb[na * 33 + b2]       = acc[nt][2];
                kb[(na + 1) * 33 + b2] = acc[nt][3];
            }
        }
        __syncthreads();

        // ---- LSTM update: thread -> (cc_u, b_u); reduce 4 k-partials ----
        float h_val, c_val;
        {
            float xi = xps[cc_u * 36 + b_u];
            float xf = xps[(8 + cc_u) * 36 + b_u];
            float xg = xps[(16 + cc_u) * 36 + b_u];
            float xo = xps[(24 + cc_u) * 36 + b_u];
#pragma unroll
            for (int k = 0; k < 4; k++) {
                const float* kb = kgb + k * (32 * 33);
                xi += kb[cc_u * 33 + b_u];
                xf += kb[(8 + cc_u) * 33 + b_u];
                xg += kb[(16 + cc_u) * 33 + b_u];
                xo += kb[(24 + cc_u) * 33 + b_u];
            }
            float ig = 1.f / (1.f + __expf(-xi));
            float fg = 1.f / (1.f + __expf(-xf));
            float gg = tanhf(xg);
            float og = 1.f / (1.f + __expf(-xo));
            c_val = fg * csl[cc_u * 32 + b_u] + ig * gg;
            csl[cc_u * 32 + b_u] = c_val;
            h_val = og * tanhf(c_val);

            // h history (protocol data) first — release depends only on this
            size_t hoff = (size_t)(dir * T_LEN + t) * (BATCH * DIM) + (size_t)b_u * DIM + j0 + cc_u;
            g_hf[hoff] = __float2half_rn(h_val);
        }

        __syncthreads();
        if (tid == 0) {
            __threadfence();
            atomicAdd(&g_sync[dir * T_LEN + s], 1);
        }

        // off-critical-path stores: fp32 output (+ finals on last step)
        out[(size_t)t * (BATCH * 1024) + (size_t)b_u * 1024 + dir * DIM + j0 + cc_u] = h_val;
        if (s == T_LEN - 1) {
            hout[((size_t)dir * BATCH + b_u) * DIM + j0 + cc_u] = h_val;
            cout[((size_t)dir * BATCH + b_u) * DIM + j0 + cc_u] = c_val;
        }
    }
}

// ---------------------------------------------------------------------------
// launch
// ---------------------------------------------------------------------------
extern "C" void kernel_launch(void* const* d_in, const int* in_sizes, int n_in,
                              void* d_out, int out_size)
{
    (void)in_sizes; (void)n_in; (void)out_size;
    const float* x   = (const float*)d_in[0];
    const float* h0  = (const float*)d_in[1];
    const float* c0  = (const float*)d_in[2];
    const float* Wih = (const float*)d_in[3];
    const float* bih = (const float*)d_in[4];
    const float* Whh = (const float*)d_in[5];
    const float* bhh = (const float*)d_in[6];

    float* out  = (float*)d_out;
    float* hout = out + (size_t)T_LEN * BATCH * 1024;
    float* cout = hout + (size_t)2 * BATCH * DIM;

    init_sync_kernel<<<4, 256>>>();

    __half *xhi, *xlo, *wf;
    cudaGetSymbolAddress((void**)&xhi, g_xhi);
    cudaGetSymbolAddress((void**)&xlo, g_xlo);
    cudaGetSymbolAddress((void**)&wf,  g_wf);
    {
        int nx = 16384 * 512;
        splith_kernel<<<nx / 4 / 256, 256>>>(x, xhi, xlo, nx);
        int nw = 4096 * 512;
        cvt_kernel<<<nw / 4 / 256, 256>>>(Wih, wf, nw);
    }

    {
        size_t smem = 4 * STAGE1;
        cudaFuncSetAttribute(xpre_mma_kernel,
                             cudaFuncAttributeMaxDynamicSharedMemorySize, (int)smem);
        dim3 grid(4096 / 128, 16384 / 128);
        xpre_mma_kernel<<<grid, 256, smem>>>(bih, bhh);
    }

    {
        cudaFuncSetAttribute(lstm_rec_mma_kernel,
                             cudaFuncAttributeMaxDynamicSharedMemorySize, SMEM2_TOTAL);
        lstm_rec_mma_kernel<<<2 * NCTA_DIR, 256, SMEM2_TOTAL>>>(h0, c0, Whh, out, hout, cout);
    }
}

// round 11
// speedup vs baseline: 1.9885x; 1.2159x over previous
#include <cuda_runtime.h>
#include <cuda_fp16.h>
#include <cstdint>

// Problem constants
#define T_LEN 512
#define BATCH 32
#define DIM   512   // D == H
#define G4    2048  // 4*H
#define NCTA_DIR 32 // recurrence CTAs per direction (16 H-cols each)
#define HCOLS 16

// Scratch
__device__ float g_xpre[(size_t)2 * T_LEN * G4 * BATCH]; // [dir][t][g][b]
__device__ int   g_sync[2 * T_LEN];                      // per-(dir,step) arrival counters

// fp16 split scratch for phase-1 GEMM: x hi/lo, W single
__device__ __half g_xhi[(size_t)16384 * 512];
__device__ __half g_xlo[(size_t)16384 * 512];
__device__ __half g_wf [(size_t)4096 * 512];

// h history: SINGLE fp16 plane [dir][t][b][512]
__device__ __half g_hf[(size_t)2 * T_LEN * BATCH * DIM];

__device__ __forceinline__ uint32_t smem_to_u32(const void* p) {
    uint32_t a;
    asm("{ .reg .u64 t; cvta.to.shared.u64 t, %1; cvt.u32.u64 %0, t; }" : "=r"(a) : "l"(p));
    return a;
}

#define CP_ASYNC16(dst, src) \
    asm volatile("cp.async.cg.shared.global [%0], [%1], 16;" :: "r"(dst), "l"(src) : "memory")
#define CP_COMMIT() asm volatile("cp.async.commit_group;" ::: "memory")
#define CP_WAIT2()  asm volatile("cp.async.wait_group 2;" ::: "memory")
#define CP_WAIT1()  asm volatile("cp.async.wait_group 1;" ::: "memory")
#define CP_WAIT0()  asm volatile("cp.async.wait_group 0;" ::: "memory")

#define LDMATRIX_X4(r0, r1, r2, r3, addr) \
    asm volatile("ldmatrix.sync.aligned.m8n8.x4.shared.b16 {%0,%1,%2,%3}, [%4];" \
        : "=r"(r0), "=r"(r1), "=r"(r2), "=r"(r3) : "r"(addr))
#define LDMATRIX_X2(r0, r1, addr) \
    asm volatile("ldmatrix.sync.aligned.m8n8.x2.shared.b16 {%0,%1}, [%2];" \
        : "=r"(r0), "=r"(r1) : "r"(addr))

#define MMA_F16(d, a, b) \
    asm volatile("mma.sync.aligned.m16n8k16.row.col.f32.f16.f16.f32 " \
        "{%0,%1,%2,%3}, {%4,%5,%6,%7}, {%8,%9}, {%0,%1,%2,%3};" \
        : "+f"((d)[0]), "+f"((d)[1]), "+f"((d)[2]), "+f"((d)[3]) \
        : "r"((a)[0]), "r"((a)[1]), "r"((a)[2]), "r"((a)[3]), "r"((b)[0]), "r"((b)[1]))

// pack two fp32 into f16x2 (low half = a, high half = b)
__device__ __forceinline__ uint32_t pack_f16(float a, float b) {
    uint32_t r;
    asm("cvt.rn.f16x2.f32 %0, %1, %2;" : "=r"(r) : "f"(b), "f"(a));
    return r;
}

// ---------------------------------------------------------------------------
__global__ void init_sync_kernel() {
    int i = blockIdx.x * blockDim.x + threadIdx.x;
    if (i < 2 * T_LEN) g_sync[i] = 0;
}

// fp32 -> fp16 hi/lo split
__global__ void splith_kernel(const float* __restrict__ src,
                              __half* __restrict__ hi,
                              __half* __restrict__ lo, int n) {
    int i = (blockIdx.x * blockDim.x + threadIdx.x) * 4;
    if (i >= n) return;
    float4 v = *(const float4*)(src + i);
    float vs[4] = {v.x, v.y, v.z, v.w};
#pragma unroll
    for (int j = 0; j < 4; j++) {
        __half h = __float2half_rn(vs[j]);
        hi[i + j] = h;
        lo[i + j] = __float2half_rn(vs[j] - __half2float(h));
    }
}

// fp32 -> fp16 single
__global__ void cvt_kernel(const float* __restrict__ src,
                           __half* __restrict__ dst, int n) {
    int i = (blockIdx.x * blockDim.x + threadIdx.x) * 4;
    if (i >= n) return;
    float4 v = *(const float4*)(src + i);
    dst[i + 0] = __float2half_rn(v.x);
    dst[i + 1] = __float2half_rn(v.y);
    dst[i + 2] = __float2half_rn(v.z);
    dst[i + 3] = __float2half_rn(v.w);
}

// ---------------------------------------------------------------------------
// Phase 1: HMMA fp16 2-pass GEMM for x_pre (measured ~555us, unchanged).
// ---------------------------------------------------------------------------
#define KC1 32
#define RPAD1 40
#define ARR1 (128 * RPAD1 * 2)
#define STAGE1 (3 * ARR1)
#define NCHUNK1 16

__global__ __launch_bounds__(256, 1)
void xpre_mma_kernel(const float* __restrict__ bih, const float* __restrict__ bhh)
{
    extern __shared__ char smem[];
    const uint32_t sb = smem_to_u32(smem);

    const int tid  = threadIdx.x;
    const int wid  = tid >> 5;
    const int lane = tid & 31;
    const int g0   = blockIdx.x * 128;
    const int m0   = blockIdx.y * 128;
    const int wg   = wid >> 1;
    const int wm   = wid & 1;

    const int grp = lane >> 2;
    const int tig = lane & 3;

    const int lrow = tid >> 1;
    const __half* gsrc[3] = {
        g_wf  + (size_t)(g0 + lrow) * 512,
        g_xhi + (size_t)(m0 + lrow) * 512,
        g_xlo + (size_t)(m0 + lrow) * 512
    };

    auto issue_chunk = [&](int kc) {
        const uint32_t stb = sb + (kc & 3) * STAGE1;
#pragma unroll
        for (int arr = 0; arr < 3; arr++) {
#pragma unroll
            for (int i = 0; i < 2; i++) {
                int seg = (tid & 1) * 2 + i;
                CP_ASYNC16(stb + arr * ARR1 + lrow * (RPAD1 * 2) + seg * 16,
                           gsrc[arr] + kc * KC1 + seg * 8);
            }
        }
        CP_COMMIT();
    };

    float acc[2][8][4];
#pragma unroll
    for (int mt = 0; mt < 2; mt++)
#pragma unroll
        for (int nt = 0; nt < 8; nt++)
#pragma unroll
            for (int r = 0; r < 4; r++) acc[mt][nt][r] = 0.f;

    issue_chunk(0);
    issue_chunk(1);
    issue_chunk(2);

    const uint32_t lm_row = (uint32_t)(lane & 15);
    const uint32_t lm_colb = (uint32_t)(lane >> 4) * 16;

    for (int kc = 0; kc < NCHUNK1; kc++) {
        const uint32_t stb = sb + (kc & 3) * STAGE1;
        CP_WAIT2();
        __syncthreads();

        const uint32_t AF  = stb;
        const uint32_t BHI = stb + ARR1;
        const uint32_t BLO = stb + 2 * ARR1;

#pragma unroll
        for (int kk = 0; kk < 2; kk++) {
            const uint32_t kb = lm_colb + kk * 32;

            uint32_t af[2][4], bb[4][4];
#pragma unroll
            for (int mt = 0; mt < 2; mt++) {
                uint32_t aoff = (wg * 32 + mt * 16 + lm_row) * (RPAD1 * 2) + kb;
                LDMATRIX_X4(af[mt][0], af[mt][1], af[mt][2], af[mt][3], AF + aoff);
            }
#pragma unroll
            for (int nt2 = 0; nt2 < 4; nt2++) {
                uint32_t boff = (wm * 64 + nt2 * 16 + lm_row) * (RPAD1 * 2) + kb;
                LDMATRIX_X4(bb[nt2][0], bb[nt2][1], bb[nt2][2], bb[nt2][3], BHI + boff);
            }
#pragma unroll
            for (int mt = 0; mt < 2; mt++)
#pragma unroll
                for (int nt = 0; nt < 8; nt++) {
                    uint32_t bfrag[2] = { bb[nt >> 1][nt & 1], bb[nt >> 1][(nt & 1) + 2] };
                    MMA_F16(acc[mt][nt], af[mt], bfrag);
                }
#pragma unroll
            for (int nt2 = 0; nt2 < 4; nt2++) {
                uint32_t boff = (wm * 64 + nt2 * 16 + lm_row) * (RPAD1 * 2) + kb;
                LDMATRIX_X4(bb[nt2][0], bb[nt2][1], bb[nt2][2], bb[nt2][3], BLO + boff);
            }
#pragma unroll
            for (int mt = 0; mt < 2; mt++)
#pragma unroll
                for (int nt = 0; nt < 8; nt++) {
                    uint32_t bfrag[2] = { bb[nt >> 1][nt & 1], bb[nt >> 1][(nt & 1) + 2] };
                    MMA_F16(acc[mt][nt], af[mt], bfrag);
                }
        }
        __syncthreads();
        if (kc + 3 < NCHUNK1) issue_chunk(kc + 3);
    }

    float bias[2][2];
    float* rowp[2][2];
#pragma unroll
    for (int mt = 0; mt < 2; mt++)
#pragma unroll
        for (int hf = 0; hf < 2; hf++) {
            int g = g0 + wg * 32 + mt * 16 + hf * 8 + grp;
            bias[mt][hf] = bih[g] + bhh[g];
            int d = g >> 11, gp = g & 2047;
            rowp[mt][hf] = g_xpre + ((size_t)d * T_LEN) * (G4 * BATCH) + (size_t)gp * BATCH;
        }
#pragma unroll
    for (int mt = 0; mt < 2; mt++)
#pragma unroll
        for (int nt = 0; nt < 8; nt++) {
            int m = m0 + wm * 64 + nt * 8 + 2 * tig;
            int t = m >> 5, b = m & 31;
            size_t toff = (size_t)t * (G4 * BATCH) + b;
            float2 v0 = { acc[mt][nt][0] + bias[mt][0], acc[mt][nt][1] + bias[mt][0] };
            float2 v1 = { acc[mt][nt][2] + bias[mt][1], acc[mt][nt][3] + bias[mt][1] };
            *(float2*)(rowp[mt][0] + toff) = v0;
            *(float2*)(rowp[mt][1] + toff) = v1;
        }
}

// ---------------------------------------------------------------------------
// Phase 2 v7: 32 CTAs/dir (16 H-cols each) -> halved L2 broadcast & arrivals.
//   W_hh single fp16 (128 preloaded B-frag regs), h single fp16.
//   Per-warp acquire polling (no tid0 relay), pipelined h load (2 k-halves),
//   c-state in registers. Warp = (mhalf, kg).
// ---------------------------------------------------------------------------
#define KPAD 520
#define WF_OFF  0
#define HF_OFF  (64 * KPAD * 2)                 // 66560
#define KGB_OFF (HF_OFF + 32 * KPAD * 2)        // 99840
#define XPS_OFF (KGB_OFF + 4 * 64 * 33 * 4)     // 133632
#define SMEM2_TOTAL (XPS_OFF + 64 * 36 * 4)     // 142848

__global__ __launch_bounds__(256, 1)
void lstm_rec_mma_kernel(const float* __restrict__ h0,
                         const float* __restrict__ c0,
                         const float* __restrict__ Whh,
                         float* __restrict__ out,
                         float* __restrict__ hout,
                         float* __restrict__ cout)
{
    extern __shared__ char smraw[];
    const uint32_t sb = smem_to_u32(smraw);
    float* kgb = (float*)(smraw + KGB_OFF);
    float* xps = (float*)(smraw + XPS_OFF);
    uint32_t* Wf32 = (uint32_t*)(smraw + WF_OFF);
    uint32_t* Hf32 = (uint32_t*)(smraw + HF_OFF);

    const int cta  = blockIdx.x;
    const int dir  = cta >> 5;
    const int j0   = (cta & (NCTA_DIR - 1)) * HCOLS;
    const int tid  = threadIdx.x;
    const int wid  = tid >> 5;
    const int lane = tid & 31;
    const int mhalf = wid >> 2;
    const int kg    = wid & 3;
    const int m0w   = mhalf * 16;

    // ---- convert W_hh slice (64 local gate rows x 512) into smem fp16 ----
    {
        int lr = tid >> 2, seg = tid & 3;  // lr 0..63, seg 0..3 (128 k each)
        int gr = (lr >> 4) * DIM + j0 + (lr & 15);
        const float4* src = (const float4*)(Whh + ((size_t)dir * G4 + gr) * DIM + seg * 128);
        uint32_t* dst = Wf32 + ((lr * KPAD + seg * 128) >> 1);
#pragma unroll
        for (int i = 0; i < 32; i++) {
            float4 v = src[i];
            dst[i * 2]     = pack_f16(v.x, v.y);
            dst[i * 2 + 1] = pack_f16(v.z, v.w);
        }
    }
    // c state in registers: cells e0 = tid, e1 = tid + 256; cell = b*16 + cc
    float c_reg[2];
#pragma unroll
    for (int e = 0; e < 2; e++) {
        int cell = tid + e * 256;
        int b = cell >> 4, cc = cell & 15;
        c_reg[e] = c0[((size_t)dir * BATCH + b) * DIM + j0 + cc];
    }
    __syncthreads();

    // ---- preload W fragments (step-invariant): bw[nt][ks][2], 128 regs ----
    uint32_t bw[8][8][2];
    {
        const uint32_t brow = (uint32_t)(lane & 7);
        const uint32_t bcol = (uint32_t)((lane >> 3) & 1) * 16;
#pragma unroll
        for (int nt = 0; nt < 8; nt++)
#pragma unroll
            for (int ks = 0; ks < 8; ks++) {
                uint32_t off = (nt * 8 + brow) * (KPAD * 2) + kg * 256 + ks * 32 + bcol;
                LDMATRIX_X2(bw[nt][ks][0], bw[nt][ks][1], sb + WF_OFF + off);
            }
    }

    const uint32_t arow_off = (uint32_t)(m0w + (lane & 15)) * (KPAD * 2)
                            + (uint32_t)kg * 256 + (uint32_t)(lane >> 4) * 16;

    const int grp = lane >> 2;
    const int tig = lane & 3;

    for (int s = 0; s < T_LEN; s++) {
        const int t = dir ? (T_LEN - 1 - s) : s;

        // prefetch x_pre slice (independent of h) BEFORE the flag wait
        {
            int lr = tid >> 2, seg = tid & 3;
            int gp = (lr >> 4) * DIM + j0 + (lr & 15);
            const float* src = g_xpre + (size_t)dir * ((size_t)T_LEN * G4 * BATCH)
                             + (size_t)t * (G4 * BATCH) + (size_t)gp * BATCH + seg * 8;
            uint32_t d = sb + XPS_OFF + (uint32_t)(lr * 144 + seg * 32);
            CP_ASYNC16(d, src);
            CP_ASYNC16(d + 16, src + 4);
            CP_COMMIT();
        }

        if (s == 0) {
            const float4* h0p = (const float4*)(h0 + (size_t)dir * BATCH * DIM);
#pragma unroll
            for (int it = 0; it < 16; it++) {
                int idx = tid + it * 256;
                int b = idx >> 7, c4 = (idx & 127) * 4;
                float4 v = h0p[idx];
                int u = (b * KPAD + c4) >> 1;
                Hf32[u]     = pack_f16(v.x, v.y);
                Hf32[u + 1] = pack_f16(v.z, v.w);
            }
            __syncthreads();
            CP_COMMIT();  // empty group so wait-count matches the s>0 path
            CP_COMMIT();
        } else {
            // per-warp acquire poll: all lanes poll same counter (broadcast)
            {
                const int* fp = &g_sync[dir * T_LEN + (s - 1)];
                int v;
                do {
                    asm volatile("ld.acquire.gpu.global.b32 %0, [%1];"
                                 : "=r"(v) : "l"(fp) : "memory");
                } while (v < NCTA_DIR);
            }
            // warp-local h cp.async: 16 batches x 128 k, in two k-halves
            const int tp = dir ? (t + 1) : (t - 1);
            const __half* hf = g_hf + (size_t)(dir * T_LEN + tp) * (BATCH * DIM);
#pragma unroll
            for (int it = 0; it < 4; it++) {   // half 1: k 0..63 of slice
                int u = lane + it * 32;
                int r = u >> 3, sg = u & 7;
                int row = m0w + r;
                size_t goff = (size_t)row * DIM + kg * 128 + sg * 8;
                uint32_t doff = (uint32_t)(row * KPAD + kg * 128 + sg * 8) * 2;
                CP_ASYNC16(sb + HF_OFF + doff, hf + goff);
            }
            CP_COMMIT();
#pragma unroll
            for (int it = 0; it < 4; it++) {   // half 2: k 64..127 of slice
                int u = lane + it * 32;
                int r = u >> 3, sg = 8 + (u & 7);
                int row = m0w + r;
                size_t goff = (size_t)row * DIM + kg * 128 + sg * 8;
                uint32_t doff = (uint32_t)(row * KPAD + kg * 128 + sg * 8) * 2;
                CP_ASYNC16(sb + HF_OFF + doff, hf + goff);
            }
            CP_COMMIT();
        }

        // ---- MMA: h @ W^T, single pass, pipelined over k-halves ----
        float acc[8][4];
#pragma unroll
        for (int nt = 0; nt < 8; nt++)
#pragma unroll
            for (int r = 0; r < 4; r++) acc[nt][r] = 0.f;

        CP_WAIT1();   // xpre + h-half1 complete (s==0: empty groups)
#pragma unroll
        for (int ks = 0; ks < 4; ks++) {
            uint32_t a_f[4];
            LDMATRIX_X4(a_f[0], a_f[1], a_f[2], a_f[3], sb + HF_OFF + arow_off + ks * 32);
#pragma unroll
            for (int nt = 0; nt < 8; nt++)
                MMA_F16(acc[nt], a_f, bw[nt][ks]);
        }
        CP_WAIT0();   // h-half2 complete
#pragma unroll
        for (int ks = 4; ks < 8; ks++) {
            uint32_t a_f[4];
            LDMATRIX_X4(a_f[0], a_f[1], a_f[2], a_f[3], sb + HF_OFF + arow_off + ks * 32);
#pragma unroll
            for (int nt = 0; nt < 8; nt++)
                MMA_F16(acc[nt], a_f, bw[nt][ks]);
        }

        // scatter partials to kgb[kg][n][b]  (n = local gate row 0..63)
        {
            float* kb = kgb + kg * (64 * 33);
            int b1 = m0w + grp, b2 = b1 + 8;
#pragma unroll
            for (int nt = 0; nt < 8; nt++) {
                int na = nt * 8 + 2 * tig;
                kb[na * 33 + b1]       = acc[nt][0];
                kb[(na + 1) * 33 + b1] = acc[nt][1];
                kb[na * 33 + b2]       = acc[nt][2];
                kb[(na + 1) * 33 + b2] = acc[nt][3];
            }
        }
        __syncthreads();

        // ---- LSTM update: 2 cells per thread; reduce 4 k-partials ----
        float h_val[2], c_new[2];
#pragma unroll
        for (int e = 0; e < 2; e++) {
            int cell = tid + e * 256;
            int b = cell >> 4, cc = cell & 15;
            float xi = xps[cc * 36 + b];
            float xf = xps[(16 + cc) * 36 + b];
            float xg = xps[(32 + cc) * 36 + b];
            float xo = xps[(48 + cc) * 36 + b];
#pragma unroll
            for (int k = 0; k < 4; k++) {
                const float* kb = kgb + k * (64 * 33);
                xi += kb[cc * 33 + b];
                xf += kb[(16 + cc) * 33 + b];
                xg += kb[(32 + cc) * 33 + b];
                xo += kb[(48 + cc) * 33 + b];
            }
            float ig = 1.f / (1.f + __expf(-xi));
            float fg = 1.f / (1.f + __expf(-xf));
            float gg = tanhf(xg);
            float og = 1.f / (1.f + __expf(-xo));
            c_new[e] = fg * c_reg[e] + ig * gg;
            c_reg[e] = c_new[e];
            h_val[e] = og * tanhf(c_new[e]);

            // h history (protocol data) first — release depends only on this
            size_t hoff = (size_t)(dir * T_LEN + t) * (BATCH * DIM)
                        + (size_t)b * DIM + j0 + cc;
            g_hf[hoff] = __float2half_rn(h_val[e]);
        }

        __syncthreads();
        if (tid == 0) {
            __threadfence();
            atomicAdd(&g_sync[dir * T_LEN + s], 1);
        }

        // off-critical-path stores: fp32 output (+ finals on last step)
#pragma unroll
        for (int e = 0; e < 2; e++) {
            int cell = tid + e * 256;
            int b = cell >> 4, cc = cell & 15;
            out[(size_t)t * (BATCH * 1024) + (size_t)b * 1024 + dir * DIM + j0 + cc] = h_val[e];
            if (s == T_LEN - 1) {
                hout[((size_t)dir * BATCH + b) * DIM + j0 + cc] = h_val[e];
                cout[((size_t)dir * BATCH + b) * DIM + j0 + cc] = c_new[e];
            }
        }
    }
}

// ---------------------------------------------------------------------------
// launch
// ---------------------------------------------------------------------------
extern "C" void kernel_launch(void* const* d_in, const int* in_sizes, int n_in,
                              void* d_out, int out_size)
{
    (void)in_sizes; (void)n_in; (void)out_size;
    const float* x   = (const float*)d_in[0];
    const float* h0  = (const float*)d_in[1];
    const float* c0  = (const float*)d_in[2];
    const float* Wih = (const float*)d_in[3];
    const float* bih = (const float*)d_in[4];
    const float* Whh = (const float*)d_in[5];
    const float* bhh = (const float*)d_in[6];

    float* out  = (float*)d_out;
    float* hout = out + (size_t)T_LEN * BATCH * 1024;
    float* cout = hout + (size_t)2 * BATCH * DIM;

    init_sync_kernel<<<4, 256>>>();

    __half *xhi, *xlo, *wf;
    cudaGetSymbolAddress((void**)&xhi, g_xhi);
    cudaGetSymbolAddress((void**)&xlo, g_xlo);
    cudaGetSymbolAddress((void**)&wf,  g_wf);
    {
        int nx = 16384 * 512;
        splith_kernel<<<nx / 4 / 256, 256>>>(x, xhi, xlo, nx);
        int nw = 4096 * 512;
        cvt_kernel<<<nw / 4 / 256, 256>>>(Wih, wf, nw);
    }

    {
        size_t smem = 4 * STAGE1;
        cudaFuncSetAttribute(xpre_mma_kernel,
                             cudaFuncAttributeMaxDynamicSharedMemorySize, (int)smem);
        dim3 grid(4096 / 128, 16384 / 128);
        xpre_mma_kernel<<<grid, 256, smem>>>(bih, bhh);
    }

    {
        cudaFuncSetAttribute(lstm_rec_mma_kernel,
                             cudaFuncAttributeMaxDynamicSharedMemorySize, SMEM2_TOTAL);
        lstm_rec_mma_kernel<<<2 * NCTA_DIR, 256, SMEM2_TOTAL>>>(h0, c0, Whh, out, hout, cout);
    }
}

// round 13
// speedup vs baseline: 2.7181x; 1.3669x over previous
#include <cuda_runtime.h>
#include <cuda_fp16.h>
#include <cstdint>

// Problem constants
#define T_LEN 512
#define BATCH 32
#define DIM   512   // D == H
#define G4    2048  // 4*H
#define NCTA_DIR 32 // recurrence CTAs per direction (16 H-cols each)
#define HCOLS 16
#define NREC  64            // recurrence CTAs total
#define NWORK 84            // GEMM worker CTAs
#define NGRID (NREC + NWORK)

// Scratch
__device__ float g_xpre[(size_t)2 * T_LEN * G4 * BATCH]; // [dir][t][g][b]
__device__ int   g_sync[2 * T_LEN];                      // recurrence step counters
__device__ int   g_xready[2 * T_LEN];                    // x_pre tile counters (full=16)

// fp16 split scratch for phase-1 GEMM: x hi/lo, W single
__device__ __half g_xhi[(size_t)16384 * 512];
__device__ __half g_xlo[(size_t)16384 * 512];
__device__ __half g_wf [(size_t)4096 * 512];

// h history: SINGLE fp16 plane [dir][t][b][512]
__device__ __half g_hf[(size_t)2 * T_LEN * BATCH * DIM];

__device__ __forceinline__ uint32_t smem_to_u32(const void* p) {
    uint32_t a;
    asm("{ .reg .u64 t; cvta.to.shared.u64 t, %1; cvt.u32.u64 %0, t; }" : "=r"(a) : "l"(p));
    return a;
}

#define CP_ASYNC16(dst, src) \
    asm volatile("cp.async.cg.shared.global [%0], [%1], 16;" :: "r"(dst), "l"(src) : "memory")
#define CP_COMMIT() asm volatile("cp.async.commit_group;" ::: "memory")
#define CP_WAIT2()  asm volatile("cp.async.wait_group 2;" ::: "memory")
#define CP_WAIT1()  asm volatile("cp.async.wait_group 1;" ::: "memory")
#define CP_WAIT0()  asm volatile("cp.async.wait_group 0;" ::: "memory")

#define LDMATRIX_X4(r0, r1, r2, r3, addr) \
    asm volatile("ldmatrix.sync.aligned.m8n8.x4.shared.b16 {%0,%1,%2,%3}, [%4];" \
        : "=r"(r0), "=r"(r1), "=r"(r2), "=r"(r3) : "r"(addr))
#define LDMATRIX_X2(r0, r1, addr) \
    asm volatile("ldmatrix.sync.aligned.m8n8.x2.shared.b16 {%0,%1}, [%2];" \
        : "=r"(r0), "=r"(r1) : "r"(addr))

#define MMA_F16(d, a, b) \
    asm volatile("mma.sync.aligned.m16n8k16.row.col.f32.f16.f16.f32 " \
        "{%0,%1,%2,%3}, {%4,%5,%6,%7}, {%8,%9}, {%0,%1,%2,%3};" \
        : "+f"((d)[0]), "+f"((d)[1]), "+f"((d)[2]), "+f"((d)[3]) \
        : "r"((a)[0]), "r"((a)[1]), "r"((a)[2]), "r"((a)[3]), "r"((b)[0]), "r"((b)[1]))

__device__ __forceinline__ uint32_t pack_f16(float a, float b) {
    uint32_t r;
    asm("cvt.rn.f16x2.f32 %0, %1, %2;" : "=r"(r) : "f"(b), "f"(a));
    return r;
}

__device__ __forceinline__ int ld_acquire(const int* p) {
    int v;
    asm volatile("ld.acquire.gpu.global.b32 %0, [%1];" : "=r"(v) : "l"(p) : "memory");
    return v;
}

// ---------------------------------------------------------------------------
__global__ void init_sync_kernel() {
    int i = blockIdx.x * blockDim.x + threadIdx.x;
    if (i < 2 * T_LEN) { g_sync[i] = 0; g_xready[i] = 0; }
}

// fp32 -> fp16 hi/lo split
__global__ void splith_kernel(const float* __restrict__ src,
                              __half* __restrict__ hi,
                              __half* __restrict__ lo, int n) {
    int i = (blockIdx.x * blockDim.x + threadIdx.x) * 4;
    if (i >= n) return;
    float4 v = *(const float4*)(src + i);
    float vs[4] = {v.x, v.y, v.z, v.w};
#pragma unroll
    for (int j = 0; j < 4; j++) {
        __half h = __float2half_rn(vs[j]);
        hi[i + j] = h;
        lo[i + j] = __float2half_rn(vs[j] - __half2float(h));
    }
}

// fp32 -> fp16 single
__global__ void cvt_kernel(const float* __restrict__ src,
                           __half* __restrict__ dst, int n) {
    int i = (blockIdx.x * blockDim.x + threadIdx.x) * 4;
    if (i >= n) return;
    float4 v = *(const float4*)(src + i);
    dst[i + 0] = __float2half_rn(v.x);
    dst[i + 1] = __float2half_rn(v.y);
    dst[i + 2] = __float2half_rn(v.z);
    dst[i + 3] = __float2half_rn(v.w);
}

// ---------------------------------------------------------------------------
// GEMM tile constants
// ---------------------------------------------------------------------------
#define KC1 32
#define RPAD1 40
#define ARR1 (128 * RPAD1 * 2)
#define STAGE1 (3 * ARR1)
#define NCHUNK1 16

// Recurrence smem layout
#define KPAD 520
#define WF_OFF  0
#define HF_OFF  (64 * KPAD * 2)                 // 66560
#define KGB_OFF (HF_OFF + 32 * KPAD * 2)        // 99840
#define XPS_OFF (KGB_OFF + 4 * 64 * 33 * 4)     // 133632
#define SMEM_TOTAL (XPS_OFF + 64 * 36 * 4)      // 142848

// ---------------------------------------------------------------------------
// GEMM worker body: processes tiles in time-priority order, signals g_xready.
// ---------------------------------------------------------------------------
__device__ void gemm_worker(char* smem, const float* __restrict__ bih,
                            const float* __restrict__ bhh, int worker)
{
    const uint32_t sb = smem_to_u32(smem);
    const int tid  = threadIdx.x;
    const int wid  = tid >> 5;
    const int lane = tid & 31;
    const int wg   = wid >> 1;
    const int wm   = wid & 1;
    const int grp  = lane >> 2;
    const int tig  = lane & 3;
    const int lrow = tid >> 1;

    const uint32_t lm_row  = (uint32_t)(lane & 15);
    const uint32_t lm_colb = (uint32_t)(lane >> 4) * 16;

    for (int idx = worker; idx < 4096; idx += NWORK) {
        const int pair = idx >> 5;     // 0..127
        const int j    = idx & 31;     // 0..31
        const int gt   = j;            // g-tile 0..31 (dir = gt>>4)
        const int mt   = (j < 16) ? pair : (127 - pair);
        const int g0   = gt * 128;
        const int m0   = mt * 128;
        const int dir  = gt >> 4;

        const __half* gsrc[3] = {
            g_wf  + (size_t)(g0 + lrow) * 512,
            g_xhi + (size_t)(m0 + lrow) * 512,
            g_xlo + (size_t)(m0 + lrow) * 512
        };

        auto issue_chunk = [&](int kc) {
            const uint32_t stb = sb + (kc & 3) * STAGE1;
#pragma unroll
            for (int arr = 0; arr < 3; arr++) {
#pragma unroll
                for (int i = 0; i < 2; i++) {
                    int seg = (tid & 1) * 2 + i;
                    CP_ASYNC16(stb + arr * ARR1 + lrow * (RPAD1 * 2) + seg * 16,
                               gsrc[arr] + kc * KC1 + seg * 8);
                }
            }
            CP_COMMIT();
        };

        float acc[2][8][4];
#pragma unroll
        for (int mtt = 0; mtt < 2; mtt++)
#pragma unroll
            for (int nt = 0; nt < 8; nt++)
#pragma unroll
                for (int r = 0; r < 4; r++) acc[mtt][nt][r] = 0.f;

        issue_chunk(0);
        issue_chunk(1);
        issue_chunk(2);

        for (int kc = 0; kc < NCHUNK1; kc++) {
            const uint32_t stb = sb + (kc & 3) * STAGE1;
            CP_WAIT2();
            __syncthreads();

            const uint32_t AF  = stb;
            const uint32_t BHI = stb + ARR1;
            const uint32_t BLO = stb + 2 * ARR1;

#pragma unroll
            for (int kk = 0; kk < 2; kk++) {
                const uint32_t kb = lm_colb + kk * 32;

                uint32_t af[2][4], bb[4][4];
#pragma unroll
                for (int mtt = 0; mtt < 2; mtt++) {
                    uint32_t aoff = (wg * 32 + mtt * 16 + lm_row) * (RPAD1 * 2) + kb;
                    LDMATRIX_X4(af[mtt][0], af[mtt][1], af[mtt][2], af[mtt][3], AF + aoff);
                }
#pragma unroll
                for (int nt2 = 0; nt2 < 4; nt2++) {
                    uint32_t boff = (wm * 64 + nt2 * 16 + lm_row) * (RPAD1 * 2) + kb;
                    LDMATRIX_X4(bb[nt2][0], bb[nt2][1], bb[nt2][2], bb[nt2][3], BHI + boff);
                }
#pragma unroll
                for (int mtt = 0; mtt < 2; mtt++)
#pragma unroll
                    for (int nt = 0; nt < 8; nt++) {
                        uint32_t bfrag[2] = { bb[nt >> 1][nt & 1], bb[nt >> 1][(nt & 1) + 2] };
                        MMA_F16(acc[mtt][nt], af[mtt], bfrag);
                    }
#pragma unroll
                for (int nt2 = 0; nt2 < 4; nt2++) {
                    uint32_t boff = (wm * 64 + nt2 * 16 + lm_row) * (RPAD1 * 2) + kb;
                    LDMATRIX_X4(bb[nt2][0], bb[nt2][1], bb[nt2][2], bb[nt2][3], BLO + boff);
                }
#pragma unroll
                for (int mtt = 0; mtt < 2; mtt++)
#pragma unroll
                    for (int nt = 0; nt < 8; nt++) {
                        uint32_t bfrag[2] = { bb[nt >> 1][nt & 1], bb[nt >> 1][(nt & 1) + 2] };
                        MMA_F16(acc[mtt][nt], af[mtt], bfrag);
                    }
            }
            __syncthreads();
            if (kc + 3 < NCHUNK1) issue_chunk(kc + 3);
        }

        // epilogue: +bias, transposed scatter
        float bias[2][2];
        float* rowp[2][2];
#pragma unroll
        for (int mtt = 0; mtt < 2; mtt++)
#pragma unroll
            for (int hf = 0; hf < 2; hf++) {
                int g = g0 + wg * 32 + mtt * 16 + hf * 8 + grp;
                bias[mtt][hf] = bih[g] + bhh[g];
                int d = g >> 11, gp = g & 2047;
                rowp[mtt][hf] = g_xpre + ((size_t)d * T_LEN) * (G4 * BATCH) + (size_t)gp * BATCH;
            }
#pragma unroll
        for (int mtt = 0; mtt < 2; mtt++)
#pragma unroll
            for (int nt = 0; nt < 8; nt++) {
                int m = m0 + wm * 64 + nt * 8 + 2 * tig;
                int t = m >> 5, b = m & 31;
                size_t toff = (size_t)t * (G4 * BATCH) + b;
                float2 v0 = { acc[mtt][nt][0] + bias[mtt][0], acc[mtt][nt][1] + bias[mtt][0] };
                float2 v1 = { acc[mtt][nt][2] + bias[mtt][1], acc[mtt][nt][3] + bias[mtt][1] };
                *(float2*)(rowp[mtt][0] + toff) = v0;
                *(float2*)(rowp[mtt][1] + toff) = v1;
            }

        // signal the 4 timesteps this m-tile covers for this dir
        __threadfence();
        __syncthreads();
        if (tid < 4)
            atomicAdd(&g_xready[dir * T_LEN + mt * 4 + tid], 1);
    }
}

// ---------------------------------------------------------------------------
// Recurrence body (R11, + x_pre readiness poll before prefetch).
// ---------------------------------------------------------------------------
__device__ void rec_body(char* smraw,
                         const float* __restrict__ h0,
                         const float* __restrict__ c0,
                         const float* __restrict__ Whh,
                         float* __restrict__ out,
                         float* __restrict__ hout,
                         float* __restrict__ cout, int cta)
{
    const uint32_t sb = smem_to_u32(smraw);
    float* kgb = (float*)(smraw + KGB_OFF);
    float* xps = (float*)(smraw + XPS_OFF);
    uint32_t* Wf32 = (uint32_t*)(smraw + WF_OFF);
    uint32_t* Hf32 = (uint32_t*)(smraw + HF_OFF);

    const int dir  = cta >> 5;
    const int j0   = (cta & (NCTA_DIR - 1)) * HCOLS;
    const int tid  = threadIdx.x;
    const int lane = tid & 31;
    const int wid  = tid >> 5;
    const int mhalf = wid >> 2;
    const int kg    = wid & 3;
    const int m0w   = mhalf * 16;

    // ---- convert W_hh slice (64 local gate rows x 512) into smem fp16 ----
    {
        int lr = tid >> 2, seg = tid & 3;
        int gr = (lr >> 4) * DIM + j0 + (lr & 15);
        const float4* src = (const float4*)(Whh + ((size_t)dir * G4 + gr) * DIM + seg * 128);
        uint32_t* dst = Wf32 + ((lr * KPAD + seg * 128) >> 1);
#pragma unroll
        for (int i = 0; i < 32; i++) {
            float4 v = src[i];
            dst[i * 2]     = pack_f16(v.x, v.y);
            dst[i * 2 + 1] = pack_f16(v.z, v.w);
        }
    }
    float c_reg[2];
#pragma unroll
    for (int e = 0; e < 2; e++) {
        int cell = tid + e * 256;
        int b = cell >> 4, cc = cell & 15;
        c_reg[e] = c0[((size_t)dir * BATCH + b) * DIM + j0 + cc];
    }
    __syncthreads();

    // ---- preload W fragments (step-invariant): bw[nt][ks][2], 128 regs ----
    uint32_t bw[8][8][2];
    {
        const uint32_t brow = (uint32_t)(lane & 7);
        const uint32_t bcol = (uint32_t)((lane >> 3) & 1) * 16;
#pragma unroll
        for (int nt = 0; nt < 8; nt++)
#pragma unroll
            for (int ks = 0; ks < 8; ks++) {
                uint32_t off = (nt * 8 + brow) * (KPAD * 2) + kg * 256 + ks * 32 + bcol;
                LDMATRIX_X2(bw[nt][ks][0], bw[nt][ks][1], sb + WF_OFF + off);
            }
    }

    const uint32_t arow_off = (uint32_t)(m0w + (lane & 15)) * (KPAD * 2)
                            + (uint32_t)kg * 256 + (uint32_t)(lane >> 4) * 16;

    const int grp = lane >> 2;
    const int tig = lane & 3;

    for (int s = 0; s < T_LEN; s++) {
        const int t = dir ? (T_LEN - 1 - s) : s;

        // wait until x_pre[dir][t] fully produced, then prefetch slice
        {
            const int* xf = &g_xready[dir * T_LEN + t];
            while (ld_acquire(xf) < 16) { }
            int lr = tid >> 2, seg = tid & 3;
            int gp = (lr >> 4) * DIM + j0 + (lr & 15);
            const float* src = g_xpre + (size_t)dir * ((size_t)T_LEN * G4 * BATCH)
                             + (size_t)t * (G4 * BATCH) + (size_t)gp * BATCH + seg * 8;
            uint32_t d = sb + XPS_OFF + (uint32_t)(lr * 144 + seg * 32);
            CP_ASYNC16(d, src);
            CP_ASYNC16(d + 16, src + 4);
            CP_COMMIT();
        }

        if (s == 0) {
            const float4* h0p = (const float4*)(h0 + (size_t)dir * BATCH * DIM);
#pragma unroll
            for (int it = 0; it < 16; it++) {
                int idx = tid + it * 256;
                int b = idx >> 7, c4 = (idx & 127) * 4;
                float4 v = h0p[idx];
                int u = (b * KPAD + c4) >> 1;
                Hf32[u]     = pack_f16(v.x, v.y);
                Hf32[u + 1] = pack_f16(v.z, v.w);
            }
            __syncthreads();
            CP_COMMIT();
            CP_COMMIT();
        } else {
            {
                const int* fp = &g_sync[dir * T_LEN + (s - 1)];
                while (ld_acquire(fp) < NCTA_DIR) { }
            }
            const int tp = dir ? (t + 1) : (t - 1);
            const __half* hf = g_hf + (size_t)(dir * T_LEN + tp) * (BATCH * DIM);
#pragma unroll
            for (int it = 0; it < 4; it++) {
                int u = lane + it * 32;
                int r = u >> 3, sg = u & 7;
                int row = m0w + r;
                size_t goff = (size_t)row * DIM + kg * 128 + sg * 8;
                uint32_t doff = (uint32_t)(row * KPAD + kg * 128 + sg * 8) * 2;
                CP_ASYNC16(sb + HF_OFF + doff, hf + goff);
            }
            CP_COMMIT();
#pragma unroll
            for (int it = 0; it < 4; it++) {
                int u = lane + it * 32;
                int r = u >> 3, sg = 8 + (u & 7);
                int row = m0w + r;
                size_t goff = (size_t)row * DIM + kg * 128 + sg * 8;
                uint32_t doff = (uint32_t)(row * KPAD + kg * 128 + sg * 8) * 2;
                CP_ASYNC16(sb + HF_OFF + doff, hf + goff);
            }
            CP_COMMIT();
        }

        // ---- MMA: h @ W^T, single pass, pipelined over k-halves ----
        float acc[8][4];
#pragma unroll
        for (int nt = 0; nt < 8; nt++)
#pragma unroll
            for (int r = 0; r < 4; r++) acc[nt][r] = 0.f;

        CP_WAIT1();
#pragma unroll
        for (int ks = 0; ks < 4; ks++) {
            uint32_t a_f[4];
            LDMATRIX_X4(a_f[0], a_f[1], a_f[2], a_f[3], sb + HF_OFF + arow_off + ks * 32);
#pragma unroll
            for (int nt = 0; nt < 8; nt++)
                MMA_F16(acc[nt], a_f, bw[nt][ks]);
        }
        CP_WAIT0();
#pragma unroll
        for (int ks = 4; ks < 8; ks++) {
            uint32_t a_f[4];
            LDMATRIX_X4(a_f[0], a_f[1], a_f[2], a_f[3], sb + HF_OFF + arow_off + ks * 32);
#pragma unroll
            for (int nt = 0; nt < 8; nt++)
                MMA_F16(acc[nt], a_f, bw[nt][ks]);
        }

        // scatter partials to kgb[kg][n][b]
        {
            float* kb = kgb + kg * (64 * 33);
            int b1 = m0w + grp, b2 = b1 + 8;
#pragma unroll
            for (int nt = 0; nt < 8; nt++) {
                int na = nt * 8 + 2 * tig;
                kb[na * 33 + b1]       = acc[nt][0];
                kb[(na + 1) * 33 + b1] = acc[nt][1];
                kb[na * 33 + b2]       = acc[nt][2];
                kb[(na + 1) * 33 + b2] = acc[nt][3];
            }
        }
        __syncthreads();

        // ---- LSTM update: 2 cells per thread; reduce 4 k-partials ----
        float h_val[2], c_new[2];
#pragma unroll
        for (int e = 0; e < 2; e++) {
            int cell = tid + e * 256;
            int b = cell >> 4, cc = cell & 15;
            float xi = xps[cc * 36 + b];
            float xf = xps[(16 + cc) * 36 + b];
            float xg = xps[(32 + cc) * 36 + b];
            float xo = xps[(48 + cc) * 36 + b];
#pragma unroll
            for (int k = 0; k < 4; k++) {
                const float* kb = kgb + k * (64 * 33);
                xi += kb[cc * 33 + b];
                xf += kb[(16 + cc) * 33 + b];
                xg += kb[(32 + cc) * 33 + b];
                xo += kb[(48 + cc) * 33 + b];
            }
            float ig = 1.f / (1.f + __expf(-xi));
            float fg = 1.f / (1.f + __expf(-xf));
            float gg = tanhf(xg);
            float og = 1.f / (1.f + __expf(-xo));
            c_new[e] = fg * c_reg[e] + ig * gg;
            c_reg[e] = c_new[e];
            h_val[e] = og * tanhf(c_new[e]);

            size_t hoff = (size_t)(dir * T_LEN + t) * (BATCH * DIM)
                        + (size_t)b * DIM + j0 + cc;
            g_hf[hoff] = __float2half_rn(h_val[e]);
        }

        __syncthreads();
        if (tid == 0) {
            __threadfence();
            atomicAdd(&g_sync[dir * T_LEN + s], 1);
        }

        // off-critical-path stores
#pragma unroll
        for (int e = 0; e < 2; e++) {
            int cell = tid + e * 256;
            int b = cell >> 4, cc = cell & 15;
            out[(size_t)t * (BATCH * 1024) + (size_t)b * 1024 + dir * DIM + j0 + cc] = h_val[e];
            if (s == T_LEN - 1) {
                hout[((size_t)dir * BATCH + b) * DIM + j0 + cc] = h_val[e];
                cout[((size_t)dir * BATCH + b) * DIM + j0 + cc] = c_new[e];
            }
        }
    }
}

// ---------------------------------------------------------------------------
// Fused persistent kernel: CTAs 0..63 recurrence, 64..147 GEMM workers.
// ---------------------------------------------------------------------------
__global__ __launch_bounds__(256, 1)
void fused_kernel(const float* __restrict__ h0,
                  const float* __restrict__ c0,
                  const float* __restrict__ Whh,
                  const float* __restrict__ bih,
                  const float* __restrict__ bhh,
                  float* __restrict__ out,
                  float* __restrict__ hout,
                  float* __restrict__ cout)
{
    extern __shared__ char smem[];
    const int cta = blockIdx.x;
    if (cta < NREC) {
        rec_body(smem, h0, c0, Whh, out, hout, cout, cta);
    } else {
        gemm_worker(smem, bih, bhh, cta - NREC);
    }
}

// ---------------------------------------------------------------------------
// launch
// ---------------------------------------------------------------------------
extern "C" void kernel_launch(void* const* d_in, const int* in_sizes, int n_in,
                              void* d_out, int out_size)
{
    (void)in_sizes; (void)n_in; (void)out_size;
    const float* x   = (const float*)d_in[0];
    const float* h0  = (const float*)d_in[1];
    const float* c0  = (const float*)d_in[2];
    const float* Wih = (const float*)d_in[3];
    const float* bih = (const float*)d_in[4];
    const float* Whh = (const float*)d_in[5];
    const float* bhh = (const float*)d_in[6];

    float* out  = (float*)d_out;
    float* hout = out + (size_t)T_LEN * BATCH * 1024;
    float* cout = hout + (size_t)2 * BATCH * DIM;

    init_sync_kernel<<<4, 256>>>();

    __half *xhi, *xlo, *wf;
    cudaGetSymbolAddress((void**)&xhi, g_xhi);
    cudaGetSymbolAddress((void**)&xlo, g_xlo);
    cudaGetSymbolAddress((void**)&wf,  g_wf);
    {
        int nx = 16384 * 512;
        splith_kernel<<<nx / 4 / 256, 256>>>(x, xhi, xlo, nx);
        int nw = 4096 * 512;
        cvt_kernel<<<nw / 4 / 256, 256>>>(Wih, wf, nw);
    }

    {
        cudaFuncSetAttribute(fused_kernel,
                             cudaFuncAttributeMaxDynamicSharedMemorySize, SMEM_TOTAL);
        fused_kernel<<<NGRID, 256, SMEM_TOTAL>>>(h0, c0, Whh, bih, bhh, out, hout, cout);
    }
}